// round 1
// baseline (speedup 1.0000x reference)
#include <cuda_runtime.h>
#include <cuda_bf16.h>
#include <math.h>

// ---- model dims ----
#define Tt   512
#define Hh   768
#define Ll   4
#define NHh  12
#define NKVv 4
#define HDd  64
#define Ee   64
#define Ff   192
#define KK   8
#define Vv   32000
#define REP  3   // NH / NKV

// ---- scratch (device globals; no allocations allowed) ----
__device__ float g_x[Tt*Hh];
__device__ float g_xn[Tt*Hh];
__device__ float g_q[Tt*NHh*HDd];
__device__ float g_k[Tt*NKVv*HDd];
__device__ float g_v[Tt*NKVv*HDd];
__device__ float g_attn[Tt*NHh*HDd];
__device__ float g_probs[Ll*Tt*Ee];
__device__ int   g_sel[Ll*Tt*KK];
__device__ float g_topw[Tt*KK];
__device__ int   g_cnt[Ee];
__device__ int   g_off[Ee+1];
__device__ int   g_fill[Ee];
__device__ int   g_pairs[Tt*KK];
__device__ float g_act[Tt*KK*Ff];
__device__ float g_slotout[Tt*KK*Hh];
__device__ float g_nll[Tt];
__device__ float g_logits_fb[(size_t)Tt*Vv];  // fallback if d_out can't hold logits

// ------------------------------------------------------------------
__global__ void k_embed(const int* __restrict__ ids, const float* __restrict__ emb){
    int t = blockIdx.x;
    int id = ids[t];
    for (int h = threadIdx.x; h < Hh; h += blockDim.x)
        g_x[t*Hh + h] = emb[(size_t)id*Hh + h];
}

__global__ void k_rmsnorm(const float* __restrict__ in, const float* __restrict__ w,
                          float* __restrict__ out){
    int t = blockIdx.x; int tid = threadIdx.x;
    __shared__ float red[256];
    float s = 0.f;
    for (int h = tid; h < Hh; h += 256){ float v = in[t*Hh + h]; s += v*v; }
    red[tid] = s; __syncthreads();
    for (int o = 128; o > 0; o >>= 1){ if (tid < o) red[tid] += red[tid+o]; __syncthreads(); }
    float r = rsqrtf(red[0] / (float)Hh + 1e-6f);
    for (int h = tid; h < Hh; h += 256)
        out[t*Hh + h] = in[t*Hh + h] * r * w[h];
}

// ---- generic SGEMM: C[M,N] (+)= A[M,K] @ B   (NT=0: B is [K,N] rm; NT=1: B is [N,K] rm)
template<int NT, int ACC>
__global__ void k_sgemm(const float* __restrict__ A, const float* __restrict__ B,
                        float* __restrict__ C, int M, int N, int K){
    __shared__ float As[16][64];
    __shared__ float Bs[16][64];
    int tid = threadIdx.x;               // 256
    int tx = tid & 15, ty = tid >> 4;
    int row0 = blockIdx.y * 64, col0 = blockIdx.x * 64;
    float acc[4][4];
    #pragma unroll
    for (int i = 0; i < 4; i++)
        #pragma unroll
        for (int j = 0; j < 4; j++) acc[i][j] = 0.f;

    int ar = tid >> 2, ak = (tid & 3) * 4;
    for (int k0 = 0; k0 < K; k0 += 16){
        float4 av = *(const float4*)&A[(size_t)(row0+ar)*K + k0 + ak];
        As[ak+0][ar]=av.x; As[ak+1][ar]=av.y; As[ak+2][ar]=av.z; As[ak+3][ar]=av.w;
        if (NT){
            float4 bv = *(const float4*)&B[(size_t)(col0+ar)*K + k0 + ak];
            Bs[ak+0][ar]=bv.x; Bs[ak+1][ar]=bv.y; Bs[ak+2][ar]=bv.z; Bs[ak+3][ar]=bv.w;
        } else {
            int bk = tid >> 4, bn = (tid & 15) * 4;
            float4 bv = *(const float4*)&B[(size_t)(k0+bk)*N + col0 + bn];
            Bs[bk][bn+0]=bv.x; Bs[bk][bn+1]=bv.y; Bs[bk][bn+2]=bv.z; Bs[bk][bn+3]=bv.w;
        }
        __syncthreads();
        #pragma unroll
        for (int kk = 0; kk < 16; kk++){
            float4 a = *(const float4*)&As[kk][ty*4];
            float4 b = *(const float4*)&Bs[kk][tx*4];
            acc[0][0]+=a.x*b.x; acc[0][1]+=a.x*b.y; acc[0][2]+=a.x*b.z; acc[0][3]+=a.x*b.w;
            acc[1][0]+=a.y*b.x; acc[1][1]+=a.y*b.y; acc[1][2]+=a.y*b.z; acc[1][3]+=a.y*b.w;
            acc[2][0]+=a.z*b.x; acc[2][1]+=a.z*b.y; acc[2][2]+=a.z*b.z; acc[2][3]+=a.z*b.w;
            acc[3][0]+=a.w*b.x; acc[3][1]+=a.w*b.y; acc[3][2]+=a.w*b.z; acc[3][3]+=a.w*b.w;
        }
        __syncthreads();
    }
    #pragma unroll
    for (int i = 0; i < 4; i++){
        int r = row0 + ty*4 + i;
        if (r >= M) continue;
        #pragma unroll
        for (int j = 0; j < 4; j++){
            int c = col0 + tx*4 + j;
            if (c >= N) continue;
            size_t idx = (size_t)r*N + c;
            if (ACC) C[idx] += acc[i][j]; else C[idx] = acc[i][j];
        }
    }
}

__global__ void k_rope(float* __restrict__ x, int nheads){
    int t = blockIdx.x, h = blockIdx.y;
    int j = threadIdx.x;                 // 32
    float expo = (float)(2*j) / 64.0f;
    float invf = 1.0f / powf(10000.0f, expo);
    float ang = (float)t * invf;
    float c = cosf(ang), s = sinf(ang);
    float* p = x + (size_t)t*nheads*HDd + h*HDd;
    float x0 = p[j], x1 = p[j+32];
    p[j]    = x0*c - x1*s;
    p[j+32] = x1*c + x0*s;
}

__global__ void k_attn(){
    int t = blockIdx.x, h = blockIdx.y;
    int kvh = h / REP;
    int tid = threadIdx.x;               // 128
    __shared__ float qs[64];
    __shared__ float p[Tt];
    __shared__ float red[128];
    if (tid < 64) qs[tid] = g_q[t*Hh + h*HDd + tid];
    __syncthreads();
    float lm = -1e30f;
    for (int kk = tid; kk <= t; kk += 128){
        const float* kr = &g_k[kk*(NKVv*HDd) + kvh*HDd];
        float s = 0.f;
        #pragma unroll
        for (int d = 0; d < 64; d++) s += qs[d]*kr[d];
        s *= 0.125f;
        p[kk] = s; lm = fmaxf(lm, s);
    }
    red[tid] = lm; __syncthreads();
    for (int o = 64; o > 0; o >>= 1){ if (tid < o) red[tid] = fmaxf(red[tid], red[tid+o]); __syncthreads(); }
    float m = red[0]; __syncthreads();
    float ls = 0.f;
    for (int kk = tid; kk <= t; kk += 128){ float e = expf(p[kk] - m); p[kk] = e; ls += e; }
    red[tid] = ls; __syncthreads();
    for (int o = 64; o > 0; o >>= 1){ if (tid < o) red[tid] += red[tid+o]; __syncthreads(); }
    float denom = red[0]; __syncthreads();
    if (tid < 64){
        float acc = 0.f;
        for (int kk = 0; kk <= t; kk++)
            acc += p[kk] * g_v[kk*(NKVv*HDd) + kvh*HDd + tid];
        g_attn[t*Hh + h*HDd + tid] = acc / denom;
    }
}

__global__ void k_router(const float* __restrict__ rw, int layer){
    int t = blockIdx.x; int e = threadIdx.x;   // 64
    __shared__ float xs[Hh];
    for (int h = e; h < Hh; h += 64) xs[h] = g_xn[t*Hh + h];
    __syncthreads();
    float acc = 0.f;
    for (int h = 0; h < Hh; h++) acc += xs[h] * rw[h*Ee + e];
    __shared__ float lg[64];
    __shared__ float red[64];
    red[e] = acc; __syncthreads();
    for (int o = 32; o > 0; o >>= 1){ if (e < o) red[e] = fmaxf(red[e], red[e+o]); __syncthreads(); }
    float m = red[0]; __syncthreads();
    float ex = expf(acc - m);
    red[e] = ex; __syncthreads();
    for (int o = 32; o > 0; o >>= 1){ if (e < o) red[e] += red[e+o]; __syncthreads(); }
    float s = red[0];
    float prob = ex / s;
    g_probs[((size_t)layer*Tt + t)*Ee + e] = prob;
    lg[e] = prob;
    __syncthreads();
    if (e == 0){
        float w[KK]; int id[KK]; float ws = 0.f;
        for (int k = 0; k < KK; k++){
            float best = -1.0f; int bi = 0;
            for (int j = 0; j < Ee; j++) if (lg[j] > best){ best = lg[j]; bi = j; }
            w[k] = best; id[k] = bi; ws += best; lg[bi] = -1.0f;
        }
        for (int k = 0; k < KK; k++){
            g_sel[((size_t)layer*Tt + t)*KK + k] = id[k];
            g_topw[t*KK + k] = w[k] / ws;
        }
    }
}

__global__ void k_count(int layer){
    __shared__ int c[64];
    int tid = threadIdx.x;
    if (tid < 64) c[tid] = 0;
    __syncthreads();
    const int* sel = &g_sel[(size_t)layer*Tt*KK];
    for (int i = tid; i < Tt*KK; i += blockDim.x) atomicAdd(&c[sel[i]], 1);
    __syncthreads();
    if (tid == 0){
        int run = 0;
        for (int e = 0; e < Ee; e++){ g_off[e] = run; run += c[e]; }
        g_off[Ee] = run;
    }
    __syncthreads();
    if (tid < 64){ g_cnt[tid] = c[tid]; g_fill[tid] = g_off[tid]; }
}

__global__ void k_scatter(int layer){
    int i = blockIdx.x*blockDim.x + threadIdx.x;
    if (i >= Tt*KK) return;
    int e = g_sel[(size_t)layer*Tt*KK + i];
    int pos = atomicAdd(&g_fill[e], 1);
    g_pairs[pos] = i;                 // packed t*8 + slot
}

__global__ void k_moe_up(const float* __restrict__ Wg, const float* __restrict__ Wu){
    int e = blockIdx.y, tile = blockIdx.x;
    int cnt = g_cnt[e];
    int br = tile*16;
    if (br >= cnt) return;
    int m = min(16, cnt - br);
    int base = g_off[e] + br;
    int tid = threadIdx.x;               // 192 (== F)
    __shared__ int toks[16];
    __shared__ float xs[16][33];
    if (tid < 16) toks[tid] = g_pairs[base + (tid < m ? tid : 0)] >> 3;
    float ag[16], au[16];
    #pragma unroll
    for (int i = 0; i < 16; i++){ ag[i] = 0.f; au[i] = 0.f; }
    const float* wg = Wg + (size_t)e*Hh*Ff;
    const float* wu = Wu + (size_t)e*Hh*Ff;
    for (int h0 = 0; h0 < Hh; h0 += 32){
        __syncthreads();
        for (int l = tid; l < 16*32; l += 192){
            int i = l >> 5, hh = l & 31;
            xs[i][hh] = g_xn[toks[i]*Hh + h0 + hh];
        }
        __syncthreads();
        #pragma unroll 8
        for (int hh = 0; hh < 32; hh++){
            float wgv = wg[(size_t)(h0+hh)*Ff + tid];
            float wuv = wu[(size_t)(h0+hh)*Ff + tid];
            #pragma unroll
            for (int i = 0; i < 16; i++){ ag[i] += xs[i][hh]*wgv; au[i] += xs[i][hh]*wuv; }
        }
    }
    for (int i = 0; i < m; i++){
        float g = ag[i];
        float sil = g / (1.0f + expf(-g));
        g_act[(size_t)(base+i)*Ff + tid] = sil * au[i];
    }
}

__global__ void k_moe_down(const float* __restrict__ Wd){
    int e = blockIdx.y, tile = blockIdx.x;
    int cnt = g_cnt[e];
    int br = tile*16;
    if (br >= cnt) return;
    int m = min(16, cnt - br);
    int base = g_off[e] + br;
    int tid = threadIdx.x;               // 768 (== H)
    __shared__ float av[16][33];
    __shared__ int prs[16];
    __shared__ float wts[16];
    if (tid < 16){
        int pr = g_pairs[base + (tid < m ? tid : 0)];
        prs[tid] = pr; wts[tid] = g_topw[pr];
    }
    float acc[16];
    #pragma unroll
    for (int i = 0; i < 16; i++) acc[i] = 0.f;
    const float* wd = Wd + (size_t)e*Ff*Hh;
    for (int f0 = 0; f0 < Ff; f0 += 32){
        __syncthreads();
        for (int l = tid; l < 16*32; l += 768){
            int i = l >> 5, ff = l & 31;
            av[i][ff] = g_act[(size_t)(base + (i < m ? i : 0))*Ff + f0 + ff];
        }
        __syncthreads();
        #pragma unroll 8
        for (int ff = 0; ff < 32; ff++){
            float w = wd[(size_t)(f0+ff)*Hh + tid];
            #pragma unroll
            for (int i = 0; i < 16; i++) acc[i] += av[i][ff]*w;
        }
    }
    for (int i = 0; i < m; i++)
        g_slotout[(size_t)prs[i]*Hh + tid] = wts[i]*acc[i];
}

__global__ void k_combine(){
    int t = blockIdx.x;
    for (int h = threadIdx.x; h < Hh; h += blockDim.x){
        float s = 0.f;
        #pragma unroll
        for (int sl = 0; sl < KK; sl++)
            s += g_slotout[(size_t)(t*KK + sl)*Hh + h];
        g_x[t*Hh + h] += s;
    }
}

__global__ void k_ce(const float* __restrict__ logits, const int* __restrict__ labels){
    int t = blockIdx.x; int tid = threadIdx.x;   // 256
    const float* row = logits + (size_t)t*Vv;
    __shared__ float red[256];
    float m = -1e30f;
    for (int v = tid; v < Vv; v += 256) m = fmaxf(m, row[v]);
    red[tid] = m; __syncthreads();
    for (int o = 128; o > 0; o >>= 1){ if (tid < o) red[tid] = fmaxf(red[tid], red[tid+o]); __syncthreads(); }
    m = red[0]; __syncthreads();
    float s = 0.f;
    for (int v = tid; v < Vv; v += 256) s += expf(row[v] - m);
    red[tid] = s; __syncthreads();
    for (int o = 128; o > 0; o >>= 1){ if (tid < o) red[tid] += red[tid+o]; __syncthreads(); }
    if (tid == 0){
        float lse = logf(red[0]) + m;
        int lbl = labels[t];
        g_nll[t] = (lbl != -100) ? (lse - row[lbl < 0 ? 0 : lbl]) : 0.0f;
    }
}

__global__ void k_final(const int* __restrict__ labels, float* lossp){
    int tid = threadIdx.x;               // 64
    __shared__ int   ccnt[64];
    __shared__ float contrib[64];
    ccnt[tid] = 0; __syncthreads();
    for (int i = tid; i < Ll*Tt*KK; i += 64) atomicAdd(&ccnt[g_sel[i]], 1);
    float sp = 0.f;
    for (int r = 0; r < Ll*Tt; r++) sp += g_probs[(size_t)r*Ee + tid];
    __syncthreads();
    contrib[tid] = sp * (float)ccnt[tid];
    __syncthreads();
    if (tid == 0){
        float aux = 0.f;
        for (int e = 0; e < Ee; e++) aux += contrib[e];
        float NN = (float)(Ll*Tt);
        aux = aux / (NN*NN) * (float)Ee;
        float ce = 0.f; int valid = 0;
        for (int t = 0; t < Tt; t++){ ce += g_nll[t]; if (labels[t] != -100) valid++; }
        ce /= (valid > 0 ? (float)valid : 1.0f);
        if (lossp) *lossp = ce + 0.01f*aux;
    }
}

// ------------------------------------------------------------------
extern "C" void kernel_launch(void* const* d_in, const int* in_sizes, int n_in,
                              void* d_out, int out_size){
    const int*   ids    = (const int*)  d_in[0];
    const int*   labels = (const int*)  d_in[1];
    const float* embed  = (const float*)d_in[2];
    const float* ln1    = (const float*)d_in[3];
    const float* Wq     = (const float*)d_in[4];
    const float* Wk     = (const float*)d_in[5];
    const float* Wv     = (const float*)d_in[6];
    const float* Wo     = (const float*)d_in[7];
    const float* ln2    = (const float*)d_in[8];
    const float* rw     = (const float*)d_in[9];
    const float* Wg     = (const float*)d_in[10];
    const float* Wu     = (const float*)d_in[11];
    const float* Wd     = (const float*)d_in[12];
    const float* fnw    = (const float*)d_in[13];

    float *xp, *xnp, *qp, *kp, *vp, *attnp, *fbp;
    cudaGetSymbolAddress((void**)&xp,    g_x);
    cudaGetSymbolAddress((void**)&xnp,   g_xn);
    cudaGetSymbolAddress((void**)&qp,    g_q);
    cudaGetSymbolAddress((void**)&kp,    g_k);
    cudaGetSymbolAddress((void**)&vp,    g_v);
    cudaGetSymbolAddress((void**)&attnp, g_attn);
    cudaGetSymbolAddress((void**)&fbp,   g_logits_fb);

    float* out = (float*)d_out;
    const size_t TV = (size_t)Tt * Vv;
    float* logits = ((size_t)out_size >= TV) ? out : fbp;
    float* lossp = nullptr;
    if ((size_t)out_size == TV + 1) lossp = out + TV;
    else if (out_size == 1)         lossp = out;

    k_embed<<<Tt, 256>>>(ids, embed);

    for (int i = 0; i < Ll; i++){
        k_rmsnorm<<<Tt, 256>>>(xp, ln1 + (size_t)i*Hh, xnp);
        k_sgemm<0,0><<<dim3(NHh*HDd/64,  Tt/64), 256>>>(xnp, Wq + (size_t)i*Hh*NHh*HDd,  qp, Tt, NHh*HDd,  Hh);
        k_sgemm<0,0><<<dim3(NKVv*HDd/64, Tt/64), 256>>>(xnp, Wk + (size_t)i*Hh*NKVv*HDd, kp, Tt, NKVv*HDd, Hh);
        k_sgemm<0,0><<<dim3(NKVv*HDd/64, Tt/64), 256>>>(xnp, Wv + (size_t)i*Hh*NKVv*HDd, vp, Tt, NKVv*HDd, Hh);
        k_rope<<<dim3(Tt, NHh),  32>>>(qp, NHh);
        k_rope<<<dim3(Tt, NKVv), 32>>>(kp, NKVv);
        k_attn<<<dim3(Tt, NHh), 128>>>();
        k_sgemm<0,1><<<dim3(Hh/64, Tt/64), 256>>>(attnp, Wo + (size_t)i*NHh*HDd*Hh, xp, Tt, Hh, Hh);
        k_rmsnorm<<<Tt, 256>>>(xp, ln2 + (size_t)i*Hh, xnp);
        k_router<<<Tt, 64>>>(rw + (size_t)i*Hh*Ee, i);
        k_count<<<1, 256>>>(i);
        k_scatter<<<16, 256>>>(i);
        k_moe_up<<<dim3(32, Ee), 192>>>(Wg, Wu);
        k_moe_down<<<dim3(32, Ee), 768>>>(Wd);
        k_combine<<<Tt, 256>>>();
    }

    k_rmsnorm<<<Tt, 256>>>(xp, fnw, xnp);
    k_sgemm<1,0><<<dim3(Vv/64, Tt/64), 256>>>(xnp, embed, logits, Tt, Vv, Hh);
    k_ce<<<Tt, 256>>>(logits, labels);
    k_final<<<1, 64>>>(labels, lossp);
}

// round 2
// speedup vs baseline: 1.1297x; 1.1297x over previous
#include <cuda_runtime.h>
#include <cuda_bf16.h>
#include <math.h>

// ---- model dims ----
#define Tt   512
#define Hh   768
#define Ll   4
#define NHh  12
#define NKVv 4
#define HDd  64
#define Ee   64
#define Ff   192
#define KK   8
#define Vv   32000
#define REP  3   // NH / NKV

// ---- scratch (device globals; no allocations allowed) ----
__device__ float g_x[Tt*Hh];
__device__ float g_xn[Tt*Hh];
__device__ float g_q[Tt*NHh*HDd];
__device__ float g_k[Tt*NKVv*HDd];
__device__ float g_v[Tt*NKVv*HDd];
__device__ float g_attn[Tt*NHh*HDd];
__device__ float g_probs[Ll*Tt*Ee];
__device__ int   g_sel[Ll*Tt*KK];
__device__ float g_topw[Tt*KK];
__device__ int   g_cnt[Ee];
__device__ int   g_off[Ee+1];
__device__ int   g_fill[Ee];
__device__ int   g_pairs[Tt*KK];
__device__ float g_act[Tt*KK*Ff];
__device__ float g_slotout[Tt*KK*Hh];
__device__ float g_nll[Tt];
__device__ float g_logits_fb[(size_t)Tt*Vv];  // fallback if d_out can't hold logits

// ------------------------------------------------------------------
// tf32 split helpers (error-compensated: a*b ~= ah*bh + ah*bl + al*bh)
__device__ __forceinline__ void split_tf32(float x, unsigned& hi, unsigned& lo){
    unsigned h; asm("cvt.rna.tf32.f32 %0, %1;" : "=r"(h) : "f"(x));
    float l = x - __uint_as_float(h);
    unsigned lb; asm("cvt.rna.tf32.f32 %0, %1;" : "=r"(lb) : "f"(l));
    hi = h; lo = lb;
}

#define MMA_TF32(d, a, b) \
    asm volatile("mma.sync.aligned.m16n8k8.row.col.f32.tf32.tf32.f32 " \
                 "{%0,%1,%2,%3},{%4,%5,%6,%7},{%8,%9},{%0,%1,%2,%3};" \
                 : "+f"(d[0]),"+f"(d[1]),"+f"(d[2]),"+f"(d[3]) \
                 : "r"(a[0]),"r"(a[1]),"r"(a[2]),"r"(a[3]),"r"(b[0]),"r"(b[1]))

// Block tile 128x64, 8 warps (4 along M, 2 along N), warp tile 32x32.
// NT=0: B is [K,N] row-major. NT=1: B is [N,K] row-major (C = A @ B^T).
// ACC=1: C += result.
template<int NT, int ACC>
__device__ __forceinline__ void mm_body(const float* __restrict__ A,
                                        const float* __restrict__ B,
                                        float* __restrict__ C,
                                        int M, int N, int K,
                                        int row0, int col0){
    __shared__ float As[128][36];     // [m][k], padded -> conflict-free frag loads
    __shared__ float Bs[2304];        // NT=1: [64][36] ; NT=0: [32][68]
    int tid  = threadIdx.x;
    int lane = tid & 31, warp = tid >> 5;
    int wm = warp & 3, wn = warp >> 2;
    int g = lane >> 2, tg = lane & 3;

    float acc[2][4][4];
    #pragma unroll
    for (int i = 0; i < 2; i++)
        #pragma unroll
        for (int j = 0; j < 4; j++)
            #pragma unroll
            for (int l = 0; l < 4; l++) acc[i][j][l] = 0.f;

    int lr = tid >> 3;            // 0..31
    int lk = (tid & 7) << 2;      // 0,4,...,28

    for (int k0 = 0; k0 < K; k0 += 32){
        __syncthreads();
        #pragma unroll
        for (int i = 0; i < 4; i++){
            float4 v = *(const float4*)&A[(size_t)(row0 + lr + i*32)*K + k0 + lk];
            *(float4*)&As[lr + i*32][lk] = v;
        }
        if (NT){
            #pragma unroll
            for (int i = 0; i < 2; i++){
                float4 v = *(const float4*)&B[(size_t)(col0 + lr + i*32)*K + k0 + lk];
                *(float4*)&Bs[(lr + i*32)*36 + lk] = v;
            }
        } else {
            int bk = tid >> 4;            // 0..15
            int bn = (tid & 15) << 2;     // 0..60
            #pragma unroll
            for (int i = 0; i < 2; i++){
                float4 v = *(const float4*)&B[(size_t)(k0 + bk + i*16)*N + col0 + bn];
                *(float4*)&Bs[(bk + i*16)*68 + bn] = v;
            }
        }
        __syncthreads();

        #pragma unroll
        for (int k8 = 0; k8 < 4; k8++){
            int kb = k8*8;
            unsigned ahi[2][4], alo[2][4], bhi[4][2], blo[4][2];
            #pragma unroll
            for (int mt = 0; mt < 2; mt++){
                int rb = wm*32 + mt*16 + g;
                float a0 = As[rb  ][kb+tg  ];
                float a1 = As[rb+8][kb+tg  ];
                float a2 = As[rb  ][kb+tg+4];
                float a3 = As[rb+8][kb+tg+4];
                split_tf32(a0, ahi[mt][0], alo[mt][0]);
                split_tf32(a1, ahi[mt][1], alo[mt][1]);
                split_tf32(a2, ahi[mt][2], alo[mt][2]);
                split_tf32(a3, ahi[mt][3], alo[mt][3]);
            }
            #pragma unroll
            for (int nt = 0; nt < 4; nt++){
                int nb = wn*32 + nt*8 + g;
                float b0, b1;
                if (NT){ b0 = Bs[nb*36 + kb+tg]; b1 = Bs[nb*36 + kb+tg+4]; }
                else   { b0 = Bs[(kb+tg)*68 + nb]; b1 = Bs[(kb+tg+4)*68 + nb]; }
                split_tf32(b0, bhi[nt][0], blo[nt][0]);
                split_tf32(b1, bhi[nt][1], blo[nt][1]);
            }
            #pragma unroll
            for (int mt = 0; mt < 2; mt++)
                #pragma unroll
                for (int nt = 0; nt < 4; nt++){
                    MMA_TF32(acc[mt][nt], ahi[mt], bhi[nt]);
                    MMA_TF32(acc[mt][nt], alo[mt], bhi[nt]);
                    MMA_TF32(acc[mt][nt], ahi[mt], blo[nt]);
                }
        }
    }

    #pragma unroll
    for (int mt = 0; mt < 2; mt++){
        int r0 = row0 + wm*32 + mt*16 + g;
        #pragma unroll
        for (int nt = 0; nt < 4; nt++){
            int c0 = col0 + wn*32 + nt*8 + tg*2;
            float* p0 = &C[(size_t)r0*N + c0];
            float* p1 = &C[(size_t)(r0+8)*N + c0];
            if (ACC){
                p0[0] += acc[mt][nt][0]; p0[1] += acc[mt][nt][1];
                p1[0] += acc[mt][nt][2]; p1[1] += acc[mt][nt][3];
            } else {
                p0[0] = acc[mt][nt][0]; p0[1] = acc[mt][nt][1];
                p1[0] = acc[mt][nt][2]; p1[1] = acc[mt][nt][3];
            }
        }
    }
}

template<int NT, int ACC>
__global__ __launch_bounds__(256, 2)
void k_mm(const float* __restrict__ A, const float* __restrict__ B,
          float* __restrict__ C, int M, int N, int K){
    mm_body<NT, ACC>(A, B, C, M, N, K, blockIdx.y*128, blockIdx.x*64);
}

// Fused QKV: one launch, grid.x covers [Wq|Wk|Wv] column tiles
__global__ __launch_bounds__(256, 2)
void k_qkv(const float* __restrict__ xn, const float* __restrict__ Wq,
           const float* __restrict__ Wk, const float* __restrict__ Wv){
    int bx = blockIdx.x;
    const float* B; float* C; int N, cb;
    if (bx < 12)      { B = Wq; C = g_q; N = 768; cb = bx; }
    else if (bx < 16) { B = Wk; C = g_k; N = 256; cb = bx - 12; }
    else              { B = Wv; C = g_v; N = 256; cb = bx - 16; }
    mm_body<0, 0>(xn, B, C, Tt, N, Hh, blockIdx.y*128, cb*64);
}

// ------------------------------------------------------------------
__global__ void k_embed(const int* __restrict__ ids, const float* __restrict__ emb){
    int t = blockIdx.x;
    int id = ids[t];
    for (int h = threadIdx.x; h < Hh; h += blockDim.x)
        g_x[t*Hh + h] = emb[(size_t)id*Hh + h];
}

__global__ void k_rmsnorm(const float* __restrict__ in, const float* __restrict__ w,
                          float* __restrict__ out){
    int t = blockIdx.x; int tid = threadIdx.x;
    __shared__ float red[256];
    float s = 0.f;
    for (int h = tid; h < Hh; h += 256){ float v = in[t*Hh + h]; s += v*v; }
    red[tid] = s; __syncthreads();
    for (int o = 128; o > 0; o >>= 1){ if (tid < o) red[tid] += red[tid+o]; __syncthreads(); }
    float r = rsqrtf(red[0] / (float)Hh + 1e-6f);
    for (int h = tid; h < Hh; h += 256)
        out[t*Hh + h] = in[t*Hh + h] * r * w[h];
}

__global__ void k_rope(float* __restrict__ x, int nheads){
    int t = blockIdx.x, h = blockIdx.y;
    int j = threadIdx.x;                 // 32
    float expo = (float)(2*j) / 64.0f;
    float invf = 1.0f / powf(10000.0f, expo);
    float ang = (float)t * invf;
    float c = cosf(ang), s = sinf(ang);
    float* p = x + (size_t)t*nheads*HDd + h*HDd;
    float x0 = p[j], x1 = p[j+32];
    p[j]    = x0*c - x1*s;
    p[j+32] = x1*c + x0*s;
}

__global__ void k_attn(){
    int t = blockIdx.x, h = blockIdx.y;
    int kvh = h / REP;
    int tid = threadIdx.x;               // 128
    __shared__ float qs[64];
    __shared__ float p[Tt];
    __shared__ float red[128];
    if (tid < 64) qs[tid] = g_q[t*Hh + h*HDd + tid];
    __syncthreads();
    float lm = -1e30f;
    for (int kk = tid; kk <= t; kk += 128){
        const float* kr = &g_k[kk*(NKVv*HDd) + kvh*HDd];
        float s = 0.f;
        #pragma unroll
        for (int d = 0; d < 64; d++) s += qs[d]*kr[d];
        s *= 0.125f;
        p[kk] = s; lm = fmaxf(lm, s);
    }
    red[tid] = lm; __syncthreads();
    for (int o = 64; o > 0; o >>= 1){ if (tid < o) red[tid] = fmaxf(red[tid], red[tid+o]); __syncthreads(); }
    float m = red[0]; __syncthreads();
    float ls = 0.f;
    for (int kk = tid; kk <= t; kk += 128){ float e = expf(p[kk] - m); p[kk] = e; ls += e; }
    red[tid] = ls; __syncthreads();
    for (int o = 64; o > 0; o >>= 1){ if (tid < o) red[tid] += red[tid+o]; __syncthreads(); }
    float denom = red[0]; __syncthreads();
    if (tid < 64){
        float acc = 0.f;
        for (int kk = 0; kk <= t; kk++)
            acc += p[kk] * g_v[kk*(NKVv*HDd) + kvh*HDd + tid];
        g_attn[t*Hh + h*HDd + tid] = acc / denom;
    }
}

__global__ void k_router(const float* __restrict__ rw, int layer){
    int t = blockIdx.x; int e = threadIdx.x;   // 64
    __shared__ float xs[Hh];
    for (int h = e; h < Hh; h += 64) xs[h] = g_xn[t*Hh + h];
    __syncthreads();
    float acc = 0.f;
    for (int h = 0; h < Hh; h++) acc += xs[h] * rw[h*Ee + e];
    __shared__ float lg[64];
    __shared__ float red[64];
    red[e] = acc; __syncthreads();
    for (int o = 32; o > 0; o >>= 1){ if (e < o) red[e] = fmaxf(red[e], red[e+o]); __syncthreads(); }
    float m = red[0]; __syncthreads();
    float ex = expf(acc - m);
    red[e] = ex; __syncthreads();
    for (int o = 32; o > 0; o >>= 1){ if (e < o) red[e] += red[e+o]; __syncthreads(); }
    float s = red[0];
    float prob = ex / s;
    g_probs[((size_t)layer*Tt + t)*Ee + e] = prob;
    lg[e] = prob;
    __syncthreads();
    if (e == 0){
        float w[KK]; int id[KK]; float ws = 0.f;
        for (int k = 0; k < KK; k++){
            float best = -1.0f; int bi = 0;
            for (int j = 0; j < Ee; j++) if (lg[j] > best){ best = lg[j]; bi = j; }
            w[k] = best; id[k] = bi; ws += best; lg[bi] = -1.0f;
        }
        for (int k = 0; k < KK; k++){
            g_sel[((size_t)layer*Tt + t)*KK + k] = id[k];
            g_topw[t*KK + k] = w[k] / ws;
        }
    }
}

__global__ void k_count(int layer){
    __shared__ int c[64];
    int tid = threadIdx.x;
    if (tid < 64) c[tid] = 0;
    __syncthreads();
    const int* sel = &g_sel[(size_t)layer*Tt*KK];
    for (int i = tid; i < Tt*KK; i += blockDim.x) atomicAdd(&c[sel[i]], 1);
    __syncthreads();
    if (tid == 0){
        int run = 0;
        for (int e = 0; e < Ee; e++){ g_off[e] = run; run += c[e]; }
        g_off[Ee] = run;
    }
    __syncthreads();
    if (tid < 64){ g_cnt[tid] = c[tid]; g_fill[tid] = g_off[tid]; }
}

__global__ void k_scatter(int layer){
    int i = blockIdx.x*blockDim.x + threadIdx.x;
    if (i >= Tt*KK) return;
    int e = g_sel[(size_t)layer*Tt*KK + i];
    int pos = atomicAdd(&g_fill[e], 1);
    g_pairs[pos] = i;                 // packed t*8 + slot
}

__global__ void k_moe_up(const float* __restrict__ Wg, const float* __restrict__ Wu){
    int e = blockIdx.y, tile = blockIdx.x;
    int cnt = g_cnt[e];
    int br = tile*16;
    if (br >= cnt) return;
    int m = min(16, cnt - br);
    int base = g_off[e] + br;
    int tid = threadIdx.x;               // 192 (== F)
    __shared__ int toks[16];
    __shared__ float xs[16][33];
    if (tid < 16) toks[tid] = g_pairs[base + (tid < m ? tid : 0)] >> 3;
    float ag[16], au[16];
    #pragma unroll
    for (int i = 0; i < 16; i++){ ag[i] = 0.f; au[i] = 0.f; }
    const float* wg = Wg + (size_t)e*Hh*Ff;
    const float* wu = Wu + (size_t)e*Hh*Ff;
    for (int h0 = 0; h0 < Hh; h0 += 32){
        __syncthreads();
        for (int l = tid; l < 16*32; l += 192){
            int i = l >> 5, hh = l & 31;
            xs[i][hh] = g_xn[toks[i]*Hh + h0 + hh];
        }
        __syncthreads();
        #pragma unroll 8
        for (int hh = 0; hh < 32; hh++){
            float wgv = wg[(size_t)(h0+hh)*Ff + tid];
            float wuv = wu[(size_t)(h0+hh)*Ff + tid];
            #pragma unroll
            for (int i = 0; i < 16; i++){ ag[i] += xs[i][hh]*wgv; au[i] += xs[i][hh]*wuv; }
        }
    }
    for (int i = 0; i < m; i++){
        float g = ag[i];
        float sil = g / (1.0f + expf(-g));
        g_act[(size_t)(base+i)*Ff + tid] = sil * au[i];
    }
}

__global__ void k_moe_down(const float* __restrict__ Wd){
    int e = blockIdx.y, tile = blockIdx.x;
    int cnt = g_cnt[e];
    int br = tile*16;
    if (br >= cnt) return;
    int m = min(16, cnt - br);
    int base = g_off[e] + br;
    int tid = threadIdx.x;               // 768 (== H)
    __shared__ float av[16][33];
    __shared__ int prs[16];
    __shared__ float wts[16];
    if (tid < 16){
        int pr = g_pairs[base + (tid < m ? tid : 0)];
        prs[tid] = pr; wts[tid] = g_topw[pr];
    }
    float acc[16];
    #pragma unroll
    for (int i = 0; i < 16; i++) acc[i] = 0.f;
    const float* wd = Wd + (size_t)e*Ff*Hh;
    for (int f0 = 0; f0 < Ff; f0 += 32){
        __syncthreads();
        for (int l = tid; l < 16*32; l += 768){
            int i = l >> 5, ff = l & 31;
            av[i][ff] = g_act[(size_t)(base + (i < m ? i : 0))*Ff + f0 + ff];
        }
        __syncthreads();
        #pragma unroll 8
        for (int ff = 0; ff < 32; ff++){
            float w = wd[(size_t)(f0+ff)*Hh + tid];
            #pragma unroll
            for (int i = 0; i < 16; i++) acc[i] += av[i][ff]*w;
        }
    }
    for (int i = 0; i < m; i++)
        g_slotout[(size_t)prs[i]*Hh + tid] = wts[i]*acc[i];
}

__global__ void k_combine(){
    int t = blockIdx.x;
    for (int h = threadIdx.x; h < Hh; h += blockDim.x){
        float s = 0.f;
        #pragma unroll
        for (int sl = 0; sl < KK; sl++)
            s += g_slotout[(size_t)(t*KK + sl)*Hh + h];
        g_x[t*Hh + h] += s;
    }
}

__global__ void k_ce(const float* __restrict__ logits, const int* __restrict__ labels){
    int t = blockIdx.x; int tid = threadIdx.x;   // 256
    const float* row = logits + (size_t)t*Vv;
    __shared__ float red[256];
    float m = -1e30f;
    for (int v = tid; v < Vv; v += 256) m = fmaxf(m, row[v]);
    red[tid] = m; __syncthreads();
    for (int o = 128; o > 0; o >>= 1){ if (tid < o) red[tid] = fmaxf(red[tid], red[tid+o]); __syncthreads(); }
    m = red[0]; __syncthreads();
    float s = 0.f;
    for (int v = tid; v < Vv; v += 256) s += expf(row[v] - m);
    red[tid] = s; __syncthreads();
    for (int o = 128; o > 0; o >>= 1){ if (tid < o) red[tid] += red[tid+o]; __syncthreads(); }
    if (tid == 0){
        float lse = logf(red[0]) + m;
        int lbl = labels[t];
        g_nll[t] = (lbl != -100) ? (lse - row[lbl < 0 ? 0 : lbl]) : 0.0f;
    }
}

__global__ void k_final(const int* __restrict__ labels, float* lossp){
    int tid = threadIdx.x;               // 64
    __shared__ int   ccnt[64];
    __shared__ float contrib[64];
    ccnt[tid] = 0; __syncthreads();
    for (int i = tid; i < Ll*Tt*KK; i += 64) atomicAdd(&ccnt[g_sel[i]], 1);
    float sp = 0.f;
    for (int r = 0; r < Ll*Tt; r++) sp += g_probs[(size_t)r*Ee + tid];
    __syncthreads();
    contrib[tid] = sp * (float)ccnt[tid];
    __syncthreads();
    if (tid == 0){
        float aux = 0.f;
        for (int e = 0; e < Ee; e++) aux += contrib[e];
        float NN = (float)(Ll*Tt);
        aux = aux / (NN*NN) * (float)Ee;
        float ce = 0.f; int valid = 0;
        for (int t = 0; t < Tt; t++){ ce += g_nll[t]; if (labels[t] != -100) valid++; }
        ce /= (valid > 0 ? (float)valid : 1.0f);
        if (lossp) *lossp = ce + 0.01f*aux;
    }
}

// ------------------------------------------------------------------
extern "C" void kernel_launch(void* const* d_in, const int* in_sizes, int n_in,
                              void* d_out, int out_size){
    const int*   ids    = (const int*)  d_in[0];
    const int*   labels = (const int*)  d_in[1];
    const float* embed  = (const float*)d_in[2];
    const float* ln1    = (const float*)d_in[3];
    const float* Wq     = (const float*)d_in[4];
    const float* Wk     = (const float*)d_in[5];
    const float* Wv     = (const float*)d_in[6];
    const float* Wo     = (const float*)d_in[7];
    const float* ln2    = (const float*)d_in[8];
    const float* rw     = (const float*)d_in[9];
    const float* Wg     = (const float*)d_in[10];
    const float* Wu     = (const float*)d_in[11];
    const float* Wd     = (const float*)d_in[12];
    const float* fnw    = (const float*)d_in[13];

    float *xp, *xnp, *qp, *kp, *vp, *attnp, *fbp;
    cudaGetSymbolAddress((void**)&xp,    g_x);
    cudaGetSymbolAddress((void**)&xnp,   g_xn);
    cudaGetSymbolAddress((void**)&qp,    g_q);
    cudaGetSymbolAddress((void**)&kp,    g_k);
    cudaGetSymbolAddress((void**)&vp,    g_v);
    cudaGetSymbolAddress((void**)&attnp, g_attn);
    cudaGetSymbolAddress((void**)&fbp,   g_logits_fb);

    float* out = (float*)d_out;
    const size_t TV = (size_t)Tt * Vv;
    float* logits = ((size_t)out_size >= TV) ? out : fbp;
    float* lossp = nullptr;
    if ((size_t)out_size == TV + 1) lossp = out + TV;
    else if (out_size == 1)         lossp = out;

    k_embed<<<Tt, 256>>>(ids, embed);

    for (int i = 0; i < Ll; i++){
        k_rmsnorm<<<Tt, 256>>>(xp, ln1 + (size_t)i*Hh, xnp);
        k_qkv<<<dim3(20, Tt/128), 256>>>(xnp, Wq + (size_t)i*Hh*NHh*HDd,
                                              Wk + (size_t)i*Hh*NKVv*HDd,
                                              Wv + (size_t)i*Hh*NKVv*HDd);
        k_rope<<<dim3(Tt, NHh),  32>>>(qp, NHh);
        k_rope<<<dim3(Tt, NKVv), 32>>>(kp, NKVv);
        k_attn<<<dim3(Tt, NHh), 128>>>();
        k_mm<0,1><<<dim3(Hh/64, Tt/128), 256>>>(attnp, Wo + (size_t)i*NHh*HDd*Hh, xp, Tt, Hh, Hh);
        k_rmsnorm<<<Tt, 256>>>(xp, ln2 + (size_t)i*Hh, xnp);
        k_router<<<Tt, 64>>>(rw + (size_t)i*Hh*Ee, i);
        k_count<<<1, 256>>>(i);
        k_scatter<<<16, 256>>>(i);
        k_moe_up<<<dim3(32, Ee), 192>>>(Wg, Wu);
        k_moe_down<<<dim3(32, Ee), 768>>>(Wd);
        k_combine<<<Tt, 256>>>();
    }

    k_rmsnorm<<<Tt, 256>>>(xp, fnw, xnp);
    k_mm<1,0><<<dim3(Vv/64, Tt/128), 256>>>(xnp, embed, logits, Tt, Vv, Hh);
    k_ce<<<Tt, 256>>>(logits, labels);
    k_final<<<1, 64>>>(labels, lossp);
}

// round 3
// speedup vs baseline: 2.0053x; 1.7751x over previous
#include <cuda_runtime.h>
#include <cuda_bf16.h>
#include <math.h>

// ---- model dims ----
#define Tt   512
#define Hh   768
#define Ll   4
#define NHh  12
#define NKVv 4
#define HDd  64
#define Ee   64
#define Ff   192
#define KK   8
#define Vv   32000
#define REP  3   // NH / NKV

// ---- scratch (device globals; no allocations allowed) ----
__device__ float g_x[Tt*Hh];
__device__ float g_xn[Tt*Hh];
__device__ float g_q[Tt*NHh*HDd];
__device__ float g_k[Tt*NKVv*HDd];
__device__ float g_v[Tt*NKVv*HDd];
__device__ float g_attn[Tt*NHh*HDd];
__device__ float g_scores[(size_t)NHh*Tt*Tt];   // 12.6 MB
__device__ float g_probs[Ll*Tt*Ee];
__device__ int   g_sel[Ll*Tt*KK];
__device__ float g_topw[Tt*KK];
__device__ int   g_cnt[Ee];
__device__ int   g_off[Ee+1];
__device__ int   g_pairs[Tt*KK];
__device__ float g_act[Tt*KK*Ff];
__device__ float g_slotout[Tt*KK*Hh];
__device__ float g_nll[Tt];
__device__ float g_logits_fb[(size_t)Tt*Vv];

// ------------------------------------------------------------------
// bf16x3 helpers: a = ah + al (ah = truncated top 16 bits, residual exact in fp32,
// al = rn(residual)); product a*b ~ ah*bh + ah*bl + al*bh  (omits ~2^-17 term)
__device__ __forceinline__ unsigned prmt_hi(unsigned a, unsigned b){
    unsigned d; asm("prmt.b32 %0,%1,%2,0x7632;" : "=r"(d) : "r"(a), "r"(b)); return d;
}
__device__ __forceinline__ unsigned pack_bf16x2(float lo, float hi){
    unsigned d; asm("cvt.rn.bf16x2.f32 %0,%1,%2;" : "=r"(d) : "f"(hi), "f"(lo)); return d;
}
__device__ __forceinline__ void split_pair(float x0, float x1, unsigned &hi, unsigned &lo){
    unsigned u0 = __float_as_uint(x0), u1 = __float_as_uint(x1);
    hi = prmt_hi(u0, u1);
    float r0 = x0 - __uint_as_float(u0 & 0xffff0000u);
    float r1 = x1 - __uint_as_float(u1 & 0xffff0000u);
    lo = pack_bf16x2(r0, r1);
}

#define MMA_BF16(d, a, b) \
    asm volatile("mma.sync.aligned.m16n8k16.row.col.f32.bf16.bf16.f32 " \
                 "{%0,%1,%2,%3},{%4,%5,%6,%7},{%8,%9},{%0,%1,%2,%3};" \
                 : "+f"(d[0]),"+f"(d[1]),"+f"(d[2]),"+f"(d[3]) \
                 : "r"(a[0]),"r"(a[1]),"r"(a[2]),"r"(a[3]),"r"(b[0]),"r"(b[1]))

// Block tile 128x64, 8 warps (4 M x 2 N), warp tile 32x32, bf16x3 MMA.
// NT=0: B is [K,N] row-major (ldb = row stride). NT=1: B is [N,K] row-major.
// Smem rows stride 20 words (40 bf16 = 80B) -> conflict-free frag loads.
template<int NT, int ACC>
__device__ __forceinline__ void mm_core(const float* __restrict__ A,
                                        const float* __restrict__ B,
                                        float* __restrict__ C,
                                        int lda, int ldb, int ldc, int K,
                                        int row0, int col0){
    __shared__ unsigned As_hi[128][20], As_lo[128][20];
    __shared__ unsigned Bs_hi[64][20],  Bs_lo[64][20];
    int tid  = threadIdx.x;
    int lane = tid & 31, warp = tid >> 5;
    int wm = warp & 3, wn = warp >> 2;
    int g = lane >> 2, tg = lane & 3;

    float acc[2][4][4];
    #pragma unroll
    for (int i = 0; i < 2; i++)
        #pragma unroll
        for (int j = 0; j < 4; j++)
            #pragma unroll
            for (int l = 0; l < 4; l++) acc[i][j][l] = 0.f;

    int lr = tid >> 3;            // 0..31
    int lk = (tid & 7) * 4;       // 0,4,...,28
    int lw = lk >> 1;             // word idx

    for (int k0 = 0; k0 < K; k0 += 32){
        __syncthreads();
        #pragma unroll
        for (int it = 0; it < 4; it++){
            int r = lr + it*32;
            float4 v = *(const float4*)&A[(size_t)(row0 + r)*lda + k0 + lk];
            unsigned h0, l0, h1, l1;
            split_pair(v.x, v.y, h0, l0);
            split_pair(v.z, v.w, h1, l1);
            As_hi[r][lw] = h0; As_hi[r][lw+1] = h1;
            As_lo[r][lw] = l0; As_lo[r][lw+1] = l1;
        }
        if (NT){
            #pragma unroll
            for (int it = 0; it < 2; it++){
                int r = lr + it*32;
                float4 v = *(const float4*)&B[(size_t)(col0 + r)*ldb + k0 + lk];
                unsigned h0, l0, h1, l1;
                split_pair(v.x, v.y, h0, l0);
                split_pair(v.z, v.w, h1, l1);
                Bs_hi[r][lw] = h0; Bs_hi[r][lw+1] = h1;
                Bs_lo[r][lw] = l0; Bs_lo[r][lw+1] = l1;
            }
        } else {
            int bn = tid & 63;
            int bk = (tid >> 6) * 4;
            #pragma unroll
            for (int p = 0; p < 2; p++){
                int kk = bk + p*16;
                const float* bp = &B[(size_t)(k0 + kk)*ldb + col0 + bn];
                float x0 = bp[0], x1 = bp[ldb], x2 = bp[2*ldb], x3 = bp[3*ldb];
                unsigned h0, l0, h1, l1;
                split_pair(x0, x1, h0, l0);
                split_pair(x2, x3, h1, l1);
                int w = kk >> 1;
                Bs_hi[bn][w] = h0; Bs_hi[bn][w+1] = h1;
                Bs_lo[bn][w] = l0; Bs_lo[bn][w+1] = l1;
            }
        }
        __syncthreads();

        #pragma unroll
        for (int s = 0; s < 2; s++){
            unsigned ah[2][4], al[2][4], bh[4][2], bl[4][2];
            int kw = 8*s + tg;
            #pragma unroll
            for (int mt = 0; mt < 2; mt++){
                int rb = wm*32 + mt*16 + g;
                ah[mt][0] = As_hi[rb][kw];    ah[mt][1] = As_hi[rb+8][kw];
                ah[mt][2] = As_hi[rb][kw+4];  ah[mt][3] = As_hi[rb+8][kw+4];
                al[mt][0] = As_lo[rb][kw];    al[mt][1] = As_lo[rb+8][kw];
                al[mt][2] = As_lo[rb][kw+4];  al[mt][3] = As_lo[rb+8][kw+4];
            }
            #pragma unroll
            for (int nt = 0; nt < 4; nt++){
                int nb = wn*32 + nt*8 + g;
                bh[nt][0] = Bs_hi[nb][kw]; bh[nt][1] = Bs_hi[nb][kw+4];
                bl[nt][0] = Bs_lo[nb][kw]; bl[nt][1] = Bs_lo[nb][kw+4];
            }
            #pragma unroll
            for (int mt = 0; mt < 2; mt++)
                #pragma unroll
                for (int nt = 0; nt < 4; nt++){
                    MMA_BF16(acc[mt][nt], ah[mt], bh[nt]);
                    MMA_BF16(acc[mt][nt], al[mt], bh[nt]);
                    MMA_BF16(acc[mt][nt], ah[mt], bl[nt]);
                }
        }
    }

    #pragma unroll
    for (int mt = 0; mt < 2; mt++){
        int r0 = row0 + wm*32 + mt*16 + g;
        #pragma unroll
        for (int nt = 0; nt < 4; nt++){
            int c0 = col0 + wn*32 + nt*8 + tg*2;
            float* p0 = &C[(size_t)r0*ldc + c0];
            float* p1 = &C[(size_t)(r0+8)*ldc + c0];
            if (ACC){
                p0[0] += acc[mt][nt][0]; p0[1] += acc[mt][nt][1];
                p1[0] += acc[mt][nt][2]; p1[1] += acc[mt][nt][3];
            } else {
                p0[0] = acc[mt][nt][0]; p0[1] = acc[mt][nt][1];
                p1[0] = acc[mt][nt][2]; p1[1] = acc[mt][nt][3];
            }
        }
    }
}

// ---- GEMM kernel instantiations ----
__global__ __launch_bounds__(256, 2)
void k_qkv(const float* __restrict__ xn, const float* __restrict__ Wq,
           const float* __restrict__ Wk, const float* __restrict__ Wv){
    int bx = blockIdx.x;
    if (bx < 12)      mm_core<0,0>(xn, Wq, g_q, Hh, NHh*HDd,  NHh*HDd,  Hh, blockIdx.y*128, bx*64);
    else if (bx < 16) mm_core<0,0>(xn, Wk, g_k, Hh, NKVv*HDd, NKVv*HDd, Hh, blockIdx.y*128, (bx-12)*64);
    else              mm_core<0,0>(xn, Wv, g_v, Hh, NKVv*HDd, NKVv*HDd, Hh, blockIdx.y*128, (bx-16)*64);
}

__global__ __launch_bounds__(256, 2)
void k_scores(){
    int h = blockIdx.z;
    if ((int)blockIdx.x >= 2*(int)blockIdx.y + 2) return;   // fully-masked tile
    mm_core<1,0>(g_q + h*HDd, g_k + (h/REP)*HDd, g_scores + (size_t)h*Tt*Tt,
                 Hh, NKVv*HDd, Tt, HDd, blockIdx.y*128, blockIdx.x*64);
}

__global__ __launch_bounds__(256, 2)
void k_pv(){
    int h = blockIdx.z;
    mm_core<0,0>(g_scores + (size_t)h*Tt*Tt, g_v + (h/REP)*HDd, g_attn + h*HDd,
                 Tt, NKVv*HDd, Hh, Tt, blockIdx.y*128, 0);
}

__global__ __launch_bounds__(256, 2)
void k_wo(const float* __restrict__ Wo){
    mm_core<0,1>(g_attn, Wo, g_x, Hh, Hh, Hh, Hh, blockIdx.y*128, blockIdx.x*64);
}

__global__ __launch_bounds__(256, 2)
void k_lmhead(const float* __restrict__ xn, const float* __restrict__ embed,
              float* __restrict__ logits){
    mm_core<1,0>(xn, embed, logits, Hh, Hh, Vv, Hh, blockIdx.y*128, blockIdx.x*64);
}

// ------------------------------------------------------------------
__global__ void k_embed(const int* __restrict__ ids, const float* __restrict__ emb){
    int t = blockIdx.x;
    int id = ids[t];
    for (int h = threadIdx.x; h < Hh; h += blockDim.x)
        g_x[t*Hh + h] = emb[(size_t)id*Hh + h];
}

__global__ void k_rmsnorm(const float* __restrict__ in, const float* __restrict__ w,
                          float* __restrict__ out){
    int t = blockIdx.x; int tid = threadIdx.x;
    __shared__ float red[256];
    float s = 0.f;
    for (int h = tid; h < Hh; h += 256){ float v = in[t*Hh + h]; s += v*v; }
    red[tid] = s; __syncthreads();
    for (int o = 128; o > 0; o >>= 1){ if (tid < o) red[tid] += red[tid+o]; __syncthreads(); }
    float r = rsqrtf(red[0] / (float)Hh + 1e-6f);
    for (int h = tid; h < Hh; h += 256)
        out[t*Hh + h] = in[t*Hh + h] * r * w[h];
}

// rope for q (12 heads) and k (4 heads) in one launch: block = 512 thr = 16 warps
__global__ void k_rope2(){
    int t = blockIdx.x;
    int w = threadIdx.x >> 5, j = threadIdx.x & 31;
    float* p = (w < 12) ? &g_q[t*Hh + w*HDd] : &g_k[t*(NKVv*HDd) + (w-12)*HDd];
    float inv = exp2f(-(float)(2*j) * (13.287712379549449f / 64.0f));
    float ang = (float)t * inv;
    float c = cosf(ang), s = sinf(ang);
    float x0 = p[j], x1 = p[j+32];
    p[j]    = x0*c - x1*s;
    p[j+32] = x1*c + x0*s;
}

// softmax of scores row (t,h): scale, causal mask, normalize; zero the tail
__global__ void k_softmax(){
    int t = blockIdx.x, h = blockIdx.y, tid = threadIdx.x;   // 128 thr
    float* row = g_scores + (size_t)h*Tt*Tt + (size_t)t*Tt;
    __shared__ float red[128];
    float m = -1e30f;
    for (int kk = tid; kk <= t; kk += 128) m = fmaxf(m, row[kk]*0.125f);
    red[tid] = m; __syncthreads();
    for (int o = 64; o > 0; o >>= 1){ if (tid < o) red[tid] = fmaxf(red[tid], red[tid+o]); __syncthreads(); }
    m = red[0]; __syncthreads();
    float s = 0.f;
    for (int kk = tid; kk <= t; kk += 128){
        float e = expf(row[kk]*0.125f - m);
        row[kk] = e; s += e;
    }
    red[tid] = s; __syncthreads();
    for (int o = 64; o > 0; o >>= 1){ if (tid < o) red[tid] += red[tid+o]; __syncthreads(); }
    float inv = 1.0f / red[0];
    for (int kk = tid; kk < Tt; kk += 128)
        row[kk] = (kk <= t) ? row[kk]*inv : 0.f;
}

// fused rmsnorm(ln2) + router (softmax + top-8) per token
__global__ void k_norm_router(const float* __restrict__ w, const float* __restrict__ rw,
                              int layer){
    int t = blockIdx.x, tid = threadIdx.x;   // 256
    __shared__ float xs[Hh];
    __shared__ float red[256];
    __shared__ float lg[64];
    float loc[3]; float ss = 0.f;
    #pragma unroll
    for (int c = 0; c < 3; c++){
        float v = g_x[t*Hh + tid + 256*c];
        loc[c] = v; ss += v*v;
    }
    red[tid] = ss; __syncthreads();
    for (int o = 128; o > 0; o >>= 1){ if (tid < o) red[tid] += red[tid+o]; __syncthreads(); }
    float r = rsqrtf(red[0] / (float)Hh + 1e-6f);
    #pragma unroll
    for (int c = 0; c < 3; c++){
        int h = tid + 256*c;
        float xn = loc[c] * r * w[h];
        xs[h] = xn; g_xn[t*Hh + h] = xn;
    }
    __syncthreads();
    if (tid < 64){
        float a0=0.f, a1=0.f, a2=0.f, a3=0.f;
        #pragma unroll 4
        for (int h = 0; h < Hh; h += 4){
            a0 += xs[h  ] * rw[(h  )*Ee + tid];
            a1 += xs[h+1] * rw[(h+1)*Ee + tid];
            a2 += xs[h+2] * rw[(h+2)*Ee + tid];
            a3 += xs[h+3] * rw[(h+3)*Ee + tid];
        }
        lg[tid] = (a0+a1) + (a2+a3);
    }
    __syncthreads();
    if (tid < 32){
        float v0 = lg[tid], v1 = lg[tid+32];
        float m = fmaxf(v0, v1);
        #pragma unroll
        for (int o = 16; o > 0; o >>= 1) m = fmaxf(m, __shfl_xor_sync(0xffffffffu, m, o));
        float e0 = expf(v0 - m), e1 = expf(v1 - m);
        float s = e0 + e1;
        #pragma unroll
        for (int o = 16; o > 0; o >>= 1) s += __shfl_xor_sync(0xffffffffu, s, o);
        float p0 = e0 / s, p1 = e1 / s;
        g_probs[((size_t)layer*Tt + t)*Ee + tid]      = p0;
        g_probs[((size_t)layer*Tt + t)*Ee + tid + 32] = p1;
        lg[tid] = p0; lg[tid+32] = p1;
        __syncwarp();
        float tv[KK]; int ti[KK]; float ws = 0.f;
        #pragma unroll
        for (int k = 0; k < KK; k++){
            float c0 = lg[tid], c1 = lg[tid+32];
            float bv; int bi;
            if (c0 >= c1){ bv = c0; bi = tid; } else { bv = c1; bi = tid+32; }
            #pragma unroll
            for (int o = 16; o > 0; o >>= 1){
                float ov = __shfl_xor_sync(0xffffffffu, bv, o);
                int   oi = __shfl_xor_sync(0xffffffffu, bi, o);
                if (ov > bv || (ov == bv && oi < bi)){ bv = ov; bi = oi; }
            }
            tv[k] = bv; ti[k] = bi; ws += bv;
            if (tid == 0) lg[bi] = -1.0f;
            __syncwarp();
        }
        if (tid == 0){
            float inv = 1.0f / ws;
            #pragma unroll
            for (int k = 0; k < KK; k++){
                g_sel[((size_t)layer*Tt + t)*KK + k] = ti[k];
                g_topw[t*KK + k] = tv[k] * inv;
            }
        }
    }
}

// fused count + exclusive scan + scatter (one block)
__global__ void k_countscatter(int layer){
    __shared__ int c[Ee], off[Ee+1], fill[Ee];
    int tid = threadIdx.x;   // 512
    if (tid < Ee) c[tid] = 0;
    __syncthreads();
    const int* sel = &g_sel[(size_t)layer*Tt*KK];
    for (int i = tid; i < Tt*KK; i += 512) atomicAdd(&c[sel[i]], 1);
    __syncthreads();
    if (tid == 0){
        int run = 0;
        for (int e = 0; e < Ee; e++){ off[e] = run; run += c[e]; }
        off[Ee] = run;
    }
    __syncthreads();
    if (tid < Ee){ g_cnt[tid] = c[tid]; g_off[tid] = off[tid]; fill[tid] = off[tid]; }
    if (tid == 0) g_off[Ee] = off[Ee];
    __syncthreads();
    for (int i = tid; i < Tt*KK; i += 512){
        int e = sel[i];
        int pos = atomicAdd(&fill[e], 1);
        g_pairs[pos] = i;
    }
}

__global__ void k_moe_up(const float* __restrict__ Wg, const float* __restrict__ Wu){
    int e = blockIdx.y, tile = blockIdx.x;
    int cnt = g_cnt[e];
    int br = tile*16;
    if (br >= cnt) return;
    int m = min(16, cnt - br);
    int base = g_off[e] + br;
    int tid = threadIdx.x;               // 192 (== F)
    __shared__ int toks[16];
    __shared__ float xs[16][33];
    if (tid < 16) toks[tid] = g_pairs[base + (tid < m ? tid : 0)] >> 3;
    float ag[16], au[16];
    #pragma unroll
    for (int i = 0; i < 16; i++){ ag[i] = 0.f; au[i] = 0.f; }
    const float* wg = Wg + (size_t)e*Hh*Ff;
    const float* wu = Wu + (size_t)e*Hh*Ff;
    for (int h0 = 0; h0 < Hh; h0 += 32){
        __syncthreads();
        for (int l = tid; l < 16*32; l += 192){
            int i = l >> 5, hh = l & 31;
            xs[i][hh] = g_xn[toks[i]*Hh + h0 + hh];
        }
        __syncthreads();
        #pragma unroll 8
        for (int hh = 0; hh < 32; hh++){
            float wgv = wg[(size_t)(h0+hh)*Ff + tid];
            float wuv = wu[(size_t)(h0+hh)*Ff + tid];
            #pragma unroll
            for (int i = 0; i < 16; i++){ ag[i] += xs[i][hh]*wgv; au[i] += xs[i][hh]*wuv; }
        }
    }
    for (int i = 0; i < m; i++){
        float g = ag[i];
        float sil = g / (1.0f + expf(-g));
        g_act[(size_t)(base+i)*Ff + tid] = sil * au[i];
    }
}

__global__ void k_moe_down(const float* __restrict__ Wd){
    int e = blockIdx.y, tile = blockIdx.x;
    int cnt = g_cnt[e];
    int br = tile*16;
    if (br >= cnt) return;
    int m = min(16, cnt - br);
    int base = g_off[e] + br;
    int tid = threadIdx.x;               // 768 (== H)
    __shared__ float av[16][33];
    __shared__ int prs[16];
    __shared__ float wts[16];
    if (tid < 16){
        int pr = g_pairs[base + (tid < m ? tid : 0)];
        prs[tid] = pr; wts[tid] = g_topw[pr];
    }
    float acc[16];
    #pragma unroll
    for (int i = 0; i < 16; i++) acc[i] = 0.f;
    const float* wd = Wd + (size_t)e*Ff*Hh;
    for (int f0 = 0; f0 < Ff; f0 += 32){
        __syncthreads();
        for (int l = tid; l < 16*32; l += 768){
            int i = l >> 5, ff = l & 31;
            av[i][ff] = g_act[(size_t)(base + (i < m ? i : 0))*Ff + f0 + ff];
        }
        __syncthreads();
        #pragma unroll 8
        for (int ff = 0; ff < 32; ff++){
            float w = wd[(size_t)(f0+ff)*Hh + tid];
            #pragma unroll
            for (int i = 0; i < 16; i++) acc[i] += av[i][ff]*w;
        }
    }
    for (int i = 0; i < m; i++)
        g_slotout[(size_t)prs[i]*Hh + tid] = wts[i]*acc[i];
}

// fused: x += sum(slots); then xn = rmsnorm(x, w)  (next ln1 or final norm)
__global__ void k_combine_norm(const float* __restrict__ w){
    int t = blockIdx.x, tid = threadIdx.x;   // 256
    __shared__ float red[256];
    float loc[3]; float ss = 0.f;
    #pragma unroll
    for (int c = 0; c < 3; c++){
        int h = tid + 256*c;
        float s = g_x[t*Hh + h];
        #pragma unroll
        for (int sl = 0; sl < KK; sl++)
            s += g_slotout[(size_t)(t*KK + sl)*Hh + h];
        g_x[t*Hh + h] = s;
        loc[c] = s; ss += s*s;
    }
    red[tid] = ss; __syncthreads();
    for (int o = 128; o > 0; o >>= 1){ if (tid < o) red[tid] += red[tid+o]; __syncthreads(); }
    float r = rsqrtf(red[0] / (float)Hh + 1e-6f);
    #pragma unroll
    for (int c = 0; c < 3; c++){
        int h = tid + 256*c;
        g_xn[t*Hh + h] = loc[c] * r * w[h];
    }
}

// single-pass online-softmax cross entropy per token
__global__ void k_ce(const float* __restrict__ logits, const int* __restrict__ labels){
    int t = blockIdx.x, tid = threadIdx.x;   // 256
    const float* row = logits + (size_t)t*Vv;
    __shared__ float rm[256], rs[256];
    float m = -1e30f, s = 0.f;
    for (int v = tid; v < Vv; v += 256){
        float x = row[v];
        float nm = fmaxf(m, x);
        s = s*expf(m - nm) + expf(x - nm);
        m = nm;
    }
    rm[tid] = m; rs[tid] = s; __syncthreads();
    for (int o = 128; o > 0; o >>= 1){
        if (tid < o){
            float m2 = rm[tid+o], s2 = rs[tid+o];
            float nm = fmaxf(rm[tid], m2);
            rs[tid] = rs[tid]*expf(rm[tid]-nm) + s2*expf(m2-nm);
            rm[tid] = nm;
        }
        __syncthreads();
    }
    if (tid == 0){
        float lse = logf(rs[0]) + rm[0];
        int lbl = labels[t];
        g_nll[t] = (lbl != -100) ? (lse - row[lbl < 0 ? 0 : lbl]) : 0.0f;
    }
}

__global__ void k_final(const int* __restrict__ labels, float* lossp){
    int tid = threadIdx.x;               // 64
    __shared__ int   ccnt[64];
    __shared__ float contrib[64];
    ccnt[tid] = 0; __syncthreads();
    for (int i = tid; i < Ll*Tt*KK; i += 64) atomicAdd(&ccnt[g_sel[i]], 1);
    float sp = 0.f;
    for (int r = 0; r < Ll*Tt; r++) sp += g_probs[(size_t)r*Ee + tid];
    __syncthreads();
    contrib[tid] = sp * (float)ccnt[tid];
    __syncthreads();
    if (tid == 0){
        float aux = 0.f;
        for (int e = 0; e < Ee; e++) aux += contrib[e];
        float NN = (float)(Ll*Tt);
        aux = aux / (NN*NN) * (float)Ee;
        float ce = 0.f; int valid = 0;
        for (int t = 0; t < Tt; t++){ ce += g_nll[t]; if (labels[t] != -100) valid++; }
        ce /= (valid > 0 ? (float)valid : 1.0f);
        if (lossp) *lossp = ce + 0.01f*aux;
    }
}

// ------------------------------------------------------------------
extern "C" void kernel_launch(void* const* d_in, const int* in_sizes, int n_in,
                              void* d_out, int out_size){
    const int*   ids    = (const int*)  d_in[0];
    const int*   labels = (const int*)  d_in[1];
    const float* embed  = (const float*)d_in[2];
    const float* ln1    = (const float*)d_in[3];
    const float* Wq     = (const float*)d_in[4];
    const float* Wk     = (const float*)d_in[5];
    const float* Wv     = (const float*)d_in[6];
    const float* Wo     = (const float*)d_in[7];
    const float* ln2    = (const float*)d_in[8];
    const float* rw     = (const float*)d_in[9];
    const float* Wg     = (const float*)d_in[10];
    const float* Wu     = (const float*)d_in[11];
    const float* Wd     = (const float*)d_in[12];
    const float* fnw    = (const float*)d_in[13];

    float *xp, *xnp, *fbp;
    cudaGetSymbolAddress((void**)&xp,  g_x);
    cudaGetSymbolAddress((void**)&xnp, g_xn);
    cudaGetSymbolAddress((void**)&fbp, g_logits_fb);

    float* out = (float*)d_out;
    const size_t TV = (size_t)Tt * Vv;
    float* logits = ((size_t)out_size >= TV) ? out : fbp;
    float* lossp = nullptr;
    if ((size_t)out_size == TV + 1) lossp = out + TV;
    else if (out_size == 1)         lossp = out;

    k_embed<<<Tt, 256>>>(ids, embed);
    k_rmsnorm<<<Tt, 256>>>(xp, ln1, xnp);

    for (int i = 0; i < Ll; i++){
        k_qkv<<<dim3(20, Tt/128), 256>>>(xnp, Wq + (size_t)i*Hh*NHh*HDd,
                                              Wk + (size_t)i*Hh*NKVv*HDd,
                                              Wv + (size_t)i*Hh*NKVv*HDd);
        k_rope2<<<Tt, 512>>>();
        k_scores<<<dim3(Tt/64, Tt/128, NHh), 256>>>();
        k_softmax<<<dim3(Tt, NHh), 128>>>();
        k_pv<<<dim3(1, Tt/128, NHh), 256>>>();
        k_wo<<<dim3(Hh/64, Tt/128), 256>>>(Wo + (size_t)i*NHh*HDd*Hh);
        k_norm_router<<<Tt, 256>>>(ln2 + (size_t)i*Hh, rw + (size_t)i*Hh*Ee, i);
        k_countscatter<<<1, 512>>>(i);
        k_moe_up<<<dim3(32, Ee), 192>>>(Wg, Wu);
        k_moe_down<<<dim3(32, Ee), 768>>>(Wd);
        const float* wnext = (i < Ll-1) ? (ln1 + (size_t)(i+1)*Hh) : fnw;
        k_combine_norm<<<Tt, 256>>>(wnext);
    }

    k_lmhead<<<dim3(Vv/64, Tt/128), 256>>>(xnp, embed, logits);
    k_ce<<<Tt, 256>>>(logits, labels);
    k_final<<<1, 64>>>(labels, lossp);
}

// round 4
// speedup vs baseline: 3.1497x; 1.5707x over previous
#include <cuda_runtime.h>
#include <cuda_bf16.h>
#include <math.h>

// ---- model dims ----
#define Tt   512
#define Hh   768
#define Ll   4
#define NHh  12
#define NKVv 4
#define HDd  64
#define Ee   64
#define Ff   192
#define KK   8
#define Vv   32000
#define REP  3   // NH / NKV
#define MAXTILES 128

// ---- scratch (device globals; no allocations allowed) ----
__device__ float g_x[Tt*Hh];
__device__ float g_xn[Tt*Hh];
__device__ float g_q[Tt*NHh*HDd];
__device__ float g_k[Tt*NKVv*HDd];
__device__ float g_v[Tt*NKVv*HDd];
__device__ float g_attn[Tt*NHh*HDd];
__device__ float g_scores[(size_t)NHh*Tt*Tt];   // 12.6 MB
__device__ float g_probs[Ll*Tt*Ee];
__device__ int   g_sel[Ll*Tt*KK];
__device__ float g_topw[Tt*KK];
__device__ int   g_cnt[Ee];
__device__ int   g_off[Ee+1];
__device__ int   g_pairs[Tt*KK];
__device__ int   g_ntiles;
__device__ int   g_tile_e[MAXTILES];
__device__ int   g_tile_base[MAXTILES];
__device__ int   g_tile_rows[MAXTILES];
__device__ float g_actg[Tt*KK*Ff];
__device__ float g_actu[Tt*KK*Ff];
__device__ float g_slotout[Tt*KK*Hh];
__device__ float g_nll[Tt];
__device__ float g_logits_fb[(size_t)Tt*Vv];

// ------------------------------------------------------------------
// bf16x3 helpers: a = ah + al (ah = truncated top 16 bits, residual exact in fp32,
// al = rn(residual)); product a*b ~ ah*bh + ah*bl + al*bh  (omits ~2^-17 term)
__device__ __forceinline__ unsigned prmt_hi(unsigned a, unsigned b){
    unsigned d; asm("prmt.b32 %0,%1,%2,0x7632;" : "=r"(d) : "r"(a), "r"(b)); return d;
}
__device__ __forceinline__ unsigned pack_bf16x2(float lo, float hi){
    unsigned d; asm("cvt.rn.bf16x2.f32 %0,%1,%2;" : "=r"(d) : "f"(hi), "f"(lo)); return d;
}
__device__ __forceinline__ void split_pair(float x0, float x1, unsigned &hi, unsigned &lo){
    unsigned u0 = __float_as_uint(x0), u1 = __float_as_uint(x1);
    hi = prmt_hi(u0, u1);
    float r0 = x0 - __uint_as_float(u0 & 0xffff0000u);
    float r1 = x1 - __uint_as_float(u1 & 0xffff0000u);
    lo = pack_bf16x2(r0, r1);
}

#define MMA_BF16(d, a, b) \
    asm volatile("mma.sync.aligned.m16n8k16.row.col.f32.bf16.bf16.f32 " \
                 "{%0,%1,%2,%3},{%4,%5,%6,%7},{%8,%9},{%0,%1,%2,%3};" \
                 : "+f"(d[0]),"+f"(d[1]),"+f"(d[2]),"+f"(d[3]) \
                 : "r"(a[0]),"r"(a[1]),"r"(a[2]),"r"(a[3]),"r"(b[0]),"r"(b[1]))

// Accumulate-only GEMM core. Block tile 128x64, 8 warps (4 M x 2 N), warp 32x32.
// A rows indirected through rowidx[] (smem, 128 entries of global row indices).
// NT=0: B is [K,N] rm; NT=1: B is [N,K] rm. AMODE=1: A elem = silu(A)*A2 on load.
template<int NT, int AMODE>
__device__ __forceinline__ void mm_acc(const float* __restrict__ A,
                                       const float* __restrict__ A2,
                                       const float* __restrict__ B,
                                       const int* __restrict__ rowidx,
                                       int lda, int ldb, int K, int col0,
                                       float acc[2][4][4],
                                       unsigned (*As_hi)[20], unsigned (*As_lo)[20],
                                       unsigned (*Bs_hi)[20], unsigned (*Bs_lo)[20]){
    int tid  = threadIdx.x;
    int lane = tid & 31, warp = tid >> 5;
    int wm = warp & 3, wn = warp >> 2;
    int gq = lane >> 2, tg = lane & 3;

    int lr = tid >> 3;            // 0..31
    int lk = (tid & 7) * 4;       // 0,4,...,28
    int lw = lk >> 1;             // word idx

    int gr[4];
    #pragma unroll
    for (int it = 0; it < 4; it++) gr[it] = rowidx[lr + it*32];

    for (int k0 = 0; k0 < K; k0 += 32){
        __syncthreads();
        #pragma unroll
        for (int it = 0; it < 4; it++){
            int r = lr + it*32;
            float4 v = *(const float4*)&A[(size_t)gr[it]*lda + k0 + lk];
            if (AMODE == 1){
                float4 u = *(const float4*)&A2[(size_t)gr[it]*lda + k0 + lk];
                v.x = v.x/(1.f+expf(-v.x))*u.x;
                v.y = v.y/(1.f+expf(-v.y))*u.y;
                v.z = v.z/(1.f+expf(-v.z))*u.z;
                v.w = v.w/(1.f+expf(-v.w))*u.w;
            }
            unsigned h0, l0, h1, l1;
            split_pair(v.x, v.y, h0, l0);
            split_pair(v.z, v.w, h1, l1);
            As_hi[r][lw] = h0; As_hi[r][lw+1] = h1;
            As_lo[r][lw] = l0; As_lo[r][lw+1] = l1;
        }
        if (NT){
            #pragma unroll
            for (int it = 0; it < 2; it++){
                int r = lr + it*32;
                float4 v = *(const float4*)&B[(size_t)(col0 + r)*ldb + k0 + lk];
                unsigned h0, l0, h1, l1;
                split_pair(v.x, v.y, h0, l0);
                split_pair(v.z, v.w, h1, l1);
                Bs_hi[r][lw] = h0; Bs_hi[r][lw+1] = h1;
                Bs_lo[r][lw] = l0; Bs_lo[r][lw+1] = l1;
            }
        } else {
            int bn = tid & 63;
            int bk = (tid >> 6) * 4;
            #pragma unroll
            for (int p = 0; p < 2; p++){
                int kk = bk + p*16;
                const float* bp = &B[(size_t)(k0 + kk)*ldb + col0 + bn];
                float x0 = bp[0], x1 = bp[ldb], x2 = bp[2*ldb], x3 = bp[3*ldb];
                unsigned h0, l0, h1, l1;
                split_pair(x0, x1, h0, l0);
                split_pair(x2, x3, h1, l1);
                int w = kk >> 1;
                Bs_hi[bn][w] = h0; Bs_hi[bn][w+1] = h1;
                Bs_lo[bn][w] = l0; Bs_lo[bn][w+1] = l1;
            }
        }
        __syncthreads();

        #pragma unroll
        for (int s = 0; s < 2; s++){
            unsigned ah[2][4], al[2][4], bh[4][2], bl[4][2];
            int kw = 8*s + tg;
            #pragma unroll
            for (int mt = 0; mt < 2; mt++){
                int rb = wm*32 + mt*16 + gq;
                ah[mt][0] = As_hi[rb][kw];    ah[mt][1] = As_hi[rb+8][kw];
                ah[mt][2] = As_hi[rb][kw+4];  ah[mt][3] = As_hi[rb+8][kw+4];
                al[mt][0] = As_lo[rb][kw];    al[mt][1] = As_lo[rb+8][kw];
                al[mt][2] = As_lo[rb][kw+4];  al[mt][3] = As_lo[rb+8][kw+4];
            }
            #pragma unroll
            for (int nt = 0; nt < 4; nt++){
                int nb = wn*32 + nt*8 + gq;
                bh[nt][0] = Bs_hi[nb][kw]; bh[nt][1] = Bs_hi[nb][kw+4];
                bl[nt][0] = Bs_lo[nb][kw]; bl[nt][1] = Bs_lo[nb][kw+4];
            }
            #pragma unroll
            for (int mt = 0; mt < 2; mt++)
                #pragma unroll
                for (int nt = 0; nt < 4; nt++){
                    MMA_BF16(acc[mt][nt], ah[mt], bh[nt]);
                    MMA_BF16(acc[mt][nt], al[mt], bh[nt]);
                    MMA_BF16(acc[mt][nt], ah[mt], bl[nt]);
                }
        }
    }
}

// Standard GEMM wrapper: C[M,N] (+)= A @ B(^T), direct store.
template<int NT, int ACC>
__device__ __forceinline__ void mm_core(const float* __restrict__ A,
                                        const float* __restrict__ B,
                                        float* __restrict__ C,
                                        int lda, int ldb, int ldc, int K,
                                        int row0, int col0){
    __shared__ unsigned As_hi[128][20], As_lo[128][20];
    __shared__ unsigned Bs_hi[64][20],  Bs_lo[64][20];
    __shared__ int rowidx[128];
    int tid = threadIdx.x;
    if (tid < 128) rowidx[tid] = row0 + tid;

    float acc[2][4][4];
    #pragma unroll
    for (int i = 0; i < 2; i++)
        #pragma unroll
        for (int j = 0; j < 4; j++)
            #pragma unroll
            for (int l = 0; l < 4; l++) acc[i][j][l] = 0.f;

    __syncthreads();
    mm_acc<NT,0>(A, nullptr, B, rowidx, lda, ldb, K, col0, acc,
                 As_hi, As_lo, Bs_hi, Bs_lo);

    int lane = tid & 31, warp = tid >> 5;
    int wm = warp & 3, wn = warp >> 2;
    int gq = lane >> 2, tg = lane & 3;
    #pragma unroll
    for (int mt = 0; mt < 2; mt++){
        int r0 = row0 + wm*32 + mt*16 + gq;
        #pragma unroll
        for (int nt = 0; nt < 4; nt++){
            int c0 = col0 + wn*32 + nt*8 + tg*2;
            float* p0 = &C[(size_t)r0*ldc + c0];
            float* p1 = &C[(size_t)(r0+8)*ldc + c0];
            if (ACC){
                p0[0] += acc[mt][nt][0]; p0[1] += acc[mt][nt][1];
                p1[0] += acc[mt][nt][2]; p1[1] += acc[mt][nt][3];
            } else {
                p0[0] = acc[mt][nt][0]; p0[1] = acc[mt][nt][1];
                p1[0] = acc[mt][nt][2]; p1[1] = acc[mt][nt][3];
            }
        }
    }
}

// ---- GEMM kernel instantiations ----
__global__ __launch_bounds__(256, 2)
void k_qkv(const float* __restrict__ xn, const float* __restrict__ Wq,
           const float* __restrict__ Wk, const float* __restrict__ Wv){
    int bx = blockIdx.x;
    if (bx < 12)      mm_core<0,0>(xn, Wq, g_q, Hh, NHh*HDd,  NHh*HDd,  Hh, blockIdx.y*128, bx*64);
    else if (bx < 16) mm_core<0,0>(xn, Wk, g_k, Hh, NKVv*HDd, NKVv*HDd, Hh, blockIdx.y*128, (bx-12)*64);
    else              mm_core<0,0>(xn, Wv, g_v, Hh, NKVv*HDd, NKVv*HDd, Hh, blockIdx.y*128, (bx-16)*64);
}

__global__ __launch_bounds__(256, 2)
void k_scores(){
    int h = blockIdx.z;
    if ((int)blockIdx.x >= 2*(int)blockIdx.y + 2) return;   // fully-masked tile
    mm_core<1,0>(g_q + h*HDd, g_k + (h/REP)*HDd, g_scores + (size_t)h*Tt*Tt,
                 Hh, NKVv*HDd, Tt, HDd, blockIdx.y*128, blockIdx.x*64);
}

__global__ __launch_bounds__(256, 2)
void k_pv(){
    int h = blockIdx.z;
    mm_core<0,0>(g_scores + (size_t)h*Tt*Tt, g_v + (h/REP)*HDd, g_attn + h*HDd,
                 Tt, NKVv*HDd, Hh, Tt, blockIdx.y*128, 0);
}

__global__ __launch_bounds__(256, 2)
void k_wo(const float* __restrict__ Wo){
    mm_core<0,1>(g_attn, Wo, g_x, Hh, Hh, Hh, Hh, blockIdx.y*128, blockIdx.x*64);
}

__global__ __launch_bounds__(256, 2)
void k_lmhead(const float* __restrict__ xn, const float* __restrict__ embed,
              float* __restrict__ logits){
    mm_core<1,0>(xn, embed, logits, Hh, Hh, Vv, Hh, blockIdx.y*128, blockIdx.x*64);
}

// ---- MoE expert GEMMs (gathered, 128-row padded tiles) ----
// up: grid (3, MAXTILES_USED, 2)  z=0 -> g (Wg), z=1 -> u (Wu). Writes raw tiles.
__global__ __launch_bounds__(256, 2)
void k_moe_up(const float* __restrict__ Wg, const float* __restrict__ Wu){
    int ti = blockIdx.y;
    if (ti >= g_ntiles) return;
    __shared__ unsigned As_hi[128][20], As_lo[128][20];
    __shared__ unsigned Bs_hi[64][20],  Bs_lo[64][20];
    __shared__ int rowidx[128];
    int e = g_tile_e[ti], base = g_tile_base[ti], rows = g_tile_rows[ti];
    int tid = threadIdx.x;
    if (tid < 128){
        int s = base + (tid < rows ? tid : rows-1);
        rowidx[tid] = g_pairs[s] >> 3;         // token index into g_xn
    }
    float acc[2][4][4];
    #pragma unroll
    for (int i = 0; i < 2; i++)
        #pragma unroll
        for (int j = 0; j < 4; j++)
            #pragma unroll
            for (int l = 0; l < 4; l++) acc[i][j][l] = 0.f;
    __syncthreads();

    const float* W = blockIdx.z ? Wu : Wg;
    int colb = blockIdx.x*64;
    mm_acc<0,0>(g_xn, nullptr, W + (size_t)e*Hh*Ff, rowidx, Hh, Ff, Hh, colb, acc,
                As_hi, As_lo, Bs_hi, Bs_lo);

    float* out = blockIdx.z ? g_actu : g_actg;
    int lane = tid & 31, warp = tid >> 5;
    int wm = warp & 3, wn = warp >> 2;
    int gq = lane >> 2, tg = lane & 3;
    #pragma unroll
    for (int mt = 0; mt < 2; mt++){
        #pragma unroll
        for (int hf = 0; hf < 2; hf++){
            int r = wm*32 + mt*16 + gq + hf*8;
            if (r < rows){
                float* op = &out[(size_t)(base + r)*Ff + colb + wn*32 + tg*2];
                #pragma unroll
                for (int nt = 0; nt < 4; nt++){
                    op[nt*8    ] = acc[mt][nt][hf*2];
                    op[nt*8 + 1] = acc[mt][nt][hf*2 + 1];
                }
            }
        }
    }
}

// down: grid (12, MAXTILES_USED). A = silu(actg)*actu (fused on load), B = Wd_e.
__global__ __launch_bounds__(256, 2)
void k_moe_down(const float* __restrict__ Wd){
    int ti = blockIdx.y;
    if (ti >= g_ntiles) return;
    __shared__ unsigned As_hi[128][20], As_lo[128][20];
    __shared__ unsigned Bs_hi[64][20],  Bs_lo[64][20];
    __shared__ int rowidx[128];
    int e = g_tile_e[ti], base = g_tile_base[ti], rows = g_tile_rows[ti];
    int tid = threadIdx.x;
    if (tid < 128)
        rowidx[tid] = base + (tid < rows ? tid : rows-1);   // slot row into act arrays
    float acc[2][4][4];
    #pragma unroll
    for (int i = 0; i < 2; i++)
        #pragma unroll
        for (int j = 0; j < 4; j++)
            #pragma unroll
            for (int l = 0; l < 4; l++) acc[i][j][l] = 0.f;
    __syncthreads();

    int colb = blockIdx.x*64;
    mm_acc<0,1>(g_actg, g_actu, Wd + (size_t)e*Ff*Hh, rowidx, Ff, Hh, Ff, colb, acc,
                As_hi, As_lo, Bs_hi, Bs_lo);

    int lane = tid & 31, warp = tid >> 5;
    int wm = warp & 3, wn = warp >> 2;
    int gq = lane >> 2, tg = lane & 3;
    #pragma unroll
    for (int mt = 0; mt < 2; mt++){
        #pragma unroll
        for (int hf = 0; hf < 2; hf++){
            int r = wm*32 + mt*16 + gq + hf*8;
            if (r < rows){
                int pr = g_pairs[base + r];
                float w = g_topw[pr];
                float* op = &g_slotout[(size_t)pr*Hh + colb + wn*32 + tg*2];
                #pragma unroll
                for (int nt = 0; nt < 4; nt++){
                    op[nt*8    ] = w*acc[mt][nt][hf*2];
                    op[nt*8 + 1] = w*acc[mt][nt][hf*2 + 1];
                }
            }
        }
    }
}

// ------------------------------------------------------------------
__global__ void k_embed(const int* __restrict__ ids, const float* __restrict__ emb){
    int t = blockIdx.x;
    int id = ids[t];
    for (int h = threadIdx.x; h < Hh; h += blockDim.x)
        g_x[t*Hh + h] = emb[(size_t)id*Hh + h];
}

__global__ void k_rmsnorm(const float* __restrict__ in, const float* __restrict__ w,
                          float* __restrict__ out){
    int t = blockIdx.x; int tid = threadIdx.x;
    __shared__ float red[256];
    float s = 0.f;
    for (int h = tid; h < Hh; h += 256){ float v = in[t*Hh + h]; s += v*v; }
    red[tid] = s; __syncthreads();
    for (int o = 128; o > 0; o >>= 1){ if (tid < o) red[tid] += red[tid+o]; __syncthreads(); }
    float r = rsqrtf(red[0] / (float)Hh + 1e-6f);
    for (int h = tid; h < Hh; h += 256)
        out[t*Hh + h] = in[t*Hh + h] * r * w[h];
}

// rope for q (12 heads) and k (4 heads) in one launch: block = 512 thr = 16 warps
__global__ void k_rope2(){
    int t = blockIdx.x;
    int w = threadIdx.x >> 5, j = threadIdx.x & 31;
    float* p = (w < 12) ? &g_q[t*Hh + w*HDd] : &g_k[t*(NKVv*HDd) + (w-12)*HDd];
    float inv = exp2f(-(float)(2*j) * (13.287712379549449f / 64.0f));
    float ang = (float)t * inv;
    float c = cosf(ang), s = sinf(ang);
    float x0 = p[j], x1 = p[j+32];
    p[j]    = x0*c - x1*s;
    p[j+32] = x1*c + x0*s;
}

// softmax of scores row (t,h): scale, causal mask, normalize; zero the tail
__global__ void k_softmax(){
    int t = blockIdx.x, h = blockIdx.y, tid = threadIdx.x;   // 128 thr
    float* row = g_scores + (size_t)h*Tt*Tt + (size_t)t*Tt;
    __shared__ float red[128];
    float m = -1e30f;
    for (int kk = tid; kk <= t; kk += 128) m = fmaxf(m, row[kk]*0.125f);
    red[tid] = m; __syncthreads();
    for (int o = 64; o > 0; o >>= 1){ if (tid < o) red[tid] = fmaxf(red[tid], red[tid+o]); __syncthreads(); }
    m = red[0]; __syncthreads();
    float s = 0.f;
    for (int kk = tid; kk <= t; kk += 128){
        float e = expf(row[kk]*0.125f - m);
        row[kk] = e; s += e;
    }
    red[tid] = s; __syncthreads();
    for (int o = 64; o > 0; o >>= 1){ if (tid < o) red[tid] += red[tid+o]; __syncthreads(); }
    float inv = 1.0f / red[0];
    for (int kk = tid; kk < Tt; kk += 128)
        row[kk] = (kk <= t) ? row[kk]*inv : 0.f;
}

// fused rmsnorm(ln2) + router (softmax + top-8) per token
__global__ void k_norm_router(const float* __restrict__ w, const float* __restrict__ rw,
                              int layer){
    int t = blockIdx.x, tid = threadIdx.x;   // 256
    __shared__ float xs[Hh];
    __shared__ float red[256];
    __shared__ float lg[64];
    float loc[3]; float ss = 0.f;
    #pragma unroll
    for (int c = 0; c < 3; c++){
        float v = g_x[t*Hh + tid + 256*c];
        loc[c] = v; ss += v*v;
    }
    red[tid] = ss; __syncthreads();
    for (int o = 128; o > 0; o >>= 1){ if (tid < o) red[tid] += red[tid+o]; __syncthreads(); }
    float r = rsqrtf(red[0] / (float)Hh + 1e-6f);
    #pragma unroll
    for (int c = 0; c < 3; c++){
        int h = tid + 256*c;
        float xn = loc[c] * r * w[h];
        xs[h] = xn; g_xn[t*Hh + h] = xn;
    }
    __syncthreads();
    if (tid < 64){
        float a0=0.f, a1=0.f, a2=0.f, a3=0.f;
        #pragma unroll 4
        for (int h = 0; h < Hh; h += 4){
            a0 += xs[h  ] * rw[(h  )*Ee + tid];
            a1 += xs[h+1] * rw[(h+1)*Ee + tid];
            a2 += xs[h+2] * rw[(h+2)*Ee + tid];
            a3 += xs[h+3] * rw[(h+3)*Ee + tid];
        }
        lg[tid] = (a0+a1) + (a2+a3);
    }
    __syncthreads();
    if (tid < 32){
        float v0 = lg[tid], v1 = lg[tid+32];
        float m = fmaxf(v0, v1);
        #pragma unroll
        for (int o = 16; o > 0; o >>= 1) m = fmaxf(m, __shfl_xor_sync(0xffffffffu, m, o));
        float e0 = expf(v0 - m), e1 = expf(v1 - m);
        float s = e0 + e1;
        #pragma unroll
        for (int o = 16; o > 0; o >>= 1) s += __shfl_xor_sync(0xffffffffu, s, o);
        float p0 = e0 / s, p1 = e1 / s;
        g_probs[((size_t)layer*Tt + t)*Ee + tid]      = p0;
        g_probs[((size_t)layer*Tt + t)*Ee + tid + 32] = p1;
        lg[tid] = p0; lg[tid+32] = p1;
        __syncwarp();
        float tv[KK]; int ti[KK]; float ws = 0.f;
        #pragma unroll
        for (int k = 0; k < KK; k++){
            float c0 = lg[tid], c1 = lg[tid+32];
            float bv; int bi;
            if (c0 >= c1){ bv = c0; bi = tid; } else { bv = c1; bi = tid+32; }
            #pragma unroll
            for (int o = 16; o > 0; o >>= 1){
                float ov = __shfl_xor_sync(0xffffffffu, bv, o);
                int   oi = __shfl_xor_sync(0xffffffffu, bi, o);
                if (ov > bv || (ov == bv && oi < bi)){ bv = ov; bi = oi; }
            }
            tv[k] = bv; ti[k] = bi; ws += bv;
            if (tid == 0) lg[bi] = -1.0f;
            __syncwarp();
        }
        if (tid == 0){
            float inv = 1.0f / ws;
            #pragma unroll
            for (int k = 0; k < KK; k++){
                g_sel[((size_t)layer*Tt + t)*KK + k] = ti[k];
                g_topw[t*KK + k] = tv[k] * inv;
            }
        }
    }
}

// fused count + exclusive scan + scatter + tile table (one block)
__global__ void k_countscatter(int layer){
    __shared__ int c[Ee], off[Ee+1], fill[Ee];
    int tid = threadIdx.x;   // 512
    if (tid < Ee) c[tid] = 0;
    __syncthreads();
    const int* sel = &g_sel[(size_t)layer*Tt*KK];
    for (int i = tid; i < Tt*KK; i += 512) atomicAdd(&c[sel[i]], 1);
    __syncthreads();
    if (tid == 0){
        int run = 0;
        for (int e = 0; e < Ee; e++){ off[e] = run; run += c[e]; }
        off[Ee] = run;
        // tile table: 128-row tiles per expert
        int n = 0;
        for (int e = 0; e < Ee; e++){
            for (int b = 0; b < c[e]; b += 128){
                g_tile_e[n] = e;
                g_tile_base[n] = off[e] + b;
                g_tile_rows[n] = min(128, c[e] - b);
                n++;
            }
        }
        g_ntiles = n;
    }
    __syncthreads();
    if (tid < Ee){ g_cnt[tid] = c[tid]; g_off[tid] = off[tid]; fill[tid] = off[tid]; }
    if (tid == 0) g_off[Ee] = off[Ee];
    __syncthreads();
    for (int i = tid; i < Tt*KK; i += 512){
        int e = sel[i];
        int pos = atomicAdd(&fill[e], 1);
        g_pairs[pos] = i;
    }
}

// fused: x += sum(slots); then xn = rmsnorm(x, w)  (next ln1 or final norm)
__global__ void k_combine_norm(const float* __restrict__ w){
    int t = blockIdx.x, tid = threadIdx.x;   // 256
    __shared__ float red[256];
    float loc[3]; float ss = 0.f;
    #pragma unroll
    for (int c = 0; c < 3; c++){
        int h = tid + 256*c;
        float s = g_x[t*Hh + h];
        #pragma unroll
        for (int sl = 0; sl < KK; sl++)
            s += g_slotout[(size_t)(t*KK + sl)*Hh + h];
        g_x[t*Hh + h] = s;
        loc[c] = s; ss += s*s;
    }
    red[tid] = ss; __syncthreads();
    for (int o = 128; o > 0; o >>= 1){ if (tid < o) red[tid] += red[tid+o]; __syncthreads(); }
    float r = rsqrtf(red[0] / (float)Hh + 1e-6f);
    #pragma unroll
    for (int c = 0; c < 3; c++){
        int h = tid + 256*c;
        g_xn[t*Hh + h] = loc[c] * r * w[h];
    }
}

// single-pass online-softmax cross entropy per token
__global__ void k_ce(const float* __restrict__ logits, const int* __restrict__ labels){
    int t = blockIdx.x, tid = threadIdx.x;   // 256
    const float* row = logits + (size_t)t*Vv;
    __shared__ float rm[256], rs[256];
    float m = -1e30f, s = 0.f;
    for (int v = tid; v < Vv; v += 256){
        float x = row[v];
        float nm = fmaxf(m, x);
        s = s*expf(m - nm) + expf(x - nm);
        m = nm;
    }
    rm[tid] = m; rs[tid] = s; __syncthreads();
    for (int o = 128; o > 0; o >>= 1){
        if (tid < o){
            float m2 = rm[tid+o], s2 = rs[tid+o];
            float nm = fmaxf(rm[tid], m2);
            rs[tid] = rs[tid]*expf(rm[tid]-nm) + s2*expf(m2-nm);
            rm[tid] = nm;
        }
        __syncthreads();
    }
    if (tid == 0){
        float lse = logf(rs[0]) + rm[0];
        int lbl = labels[t];
        g_nll[t] = (lbl != -100) ? (lse - row[lbl < 0 ? 0 : lbl]) : 0.0f;
    }
}

__global__ void k_final(const int* __restrict__ labels, float* lossp){
    int tid = threadIdx.x;               // 64
    __shared__ int   ccnt[64];
    __shared__ float contrib[64];
    ccnt[tid] = 0; __syncthreads();
    for (int i = tid; i < Ll*Tt*KK; i += 64) atomicAdd(&ccnt[g_sel[i]], 1);
    float sp = 0.f;
    for (int r = 0; r < Ll*Tt; r++) sp += g_probs[(size_t)r*Ee + tid];
    __syncthreads();
    contrib[tid] = sp * (float)ccnt[tid];
    __syncthreads();
    if (tid == 0){
        float aux = 0.f;
        for (int e = 0; e < Ee; e++) aux += contrib[e];
        float NN = (float)(Ll*Tt);
        aux = aux / (NN*NN) * (float)Ee;
        float ce = 0.f; int valid = 0;
        for (int t = 0; t < Tt; t++){ ce += g_nll[t]; if (labels[t] != -100) valid++; }
        ce /= (valid > 0 ? (float)valid : 1.0f);
        if (lossp) *lossp = ce + 0.01f*aux;
    }
}

// ------------------------------------------------------------------
extern "C" void kernel_launch(void* const* d_in, const int* in_sizes, int n_in,
                              void* d_out, int out_size){
    const int*   ids    = (const int*)  d_in[0];
    const int*   labels = (const int*)  d_in[1];
    const float* embed  = (const float*)d_in[2];
    const float* ln1    = (const float*)d_in[3];
    const float* Wq     = (const float*)d_in[4];
    const float* Wk     = (const float*)d_in[5];
    const float* Wv     = (const float*)d_in[6];
    const float* Wo     = (const float*)d_in[7];
    const float* ln2    = (const float*)d_in[8];
    const float* rw     = (const float*)d_in[9];
    const float* Wg     = (const float*)d_in[10];
    const float* Wu     = (const float*)d_in[11];
    const float* Wd     = (const float*)d_in[12];
    const float* fnw    = (const float*)d_in[13];

    float *xp, *xnp, *fbp;
    cudaGetSymbolAddress((void**)&xp,  g_x);
    cudaGetSymbolAddress((void**)&xnp, g_xn);
    cudaGetSymbolAddress((void**)&fbp, g_logits_fb);

    float* out = (float*)d_out;
    const size_t TV = (size_t)Tt * Vv;
    float* logits = ((size_t)out_size >= TV) ? out : fbp;
    float* lossp = nullptr;
    if ((size_t)out_size == TV + 1) lossp = out + TV;
    else if (out_size == 1)         lossp = out;

    k_embed<<<Tt, 256>>>(ids, embed);
    k_rmsnorm<<<Tt, 256>>>(xp, ln1, xnp);

    for (int i = 0; i < Ll; i++){
        k_qkv<<<dim3(20, Tt/128), 256>>>(xnp, Wq + (size_t)i*Hh*NHh*HDd,
                                              Wk + (size_t)i*Hh*NKVv*HDd,
                                              Wv + (size_t)i*Hh*NKVv*HDd);
        k_rope2<<<Tt, 512>>>();
        k_scores<<<dim3(Tt/64, Tt/128, NHh), 256>>>();
        k_softmax<<<dim3(Tt, NHh), 128>>>();
        k_pv<<<dim3(1, Tt/128, NHh), 256>>>();
        k_wo<<<dim3(Hh/64, Tt/128), 256>>>(Wo + (size_t)i*NHh*HDd*Hh);
        k_norm_router<<<Tt, 256>>>(ln2 + (size_t)i*Hh, rw + (size_t)i*Hh*Ee, i);
        k_countscatter<<<1, 512>>>(i);
        k_moe_up<<<dim3(3, 96, 2), 256>>>(Wg, Wu);
        k_moe_down<<<dim3(12, 96), 256>>>(Wd);
        const float* wnext = (i < Ll-1) ? (ln1 + (size_t)(i+1)*Hh) : fnw;
        k_combine_norm<<<Tt, 256>>>(wnext);
    }

    k_lmhead<<<dim3(Vv/64, Tt/128), 256>>>(xnp, embed, logits);
    k_ce<<<Tt, 256>>>(logits, labels);
    k_final<<<1, 64>>>(labels, lossp);
}